// round 10
// baseline (speedup 1.0000x reference)
#include <cuda_runtime.h>
#include <cuda_fp16.h>
#include <cstdint>

// Problem constants
#define BATCH 2
#define NSEQ  2048
#define DMODEL 1024
#define NHEAD 16
#define DK    64
#define MROWS (BATCH * NSEQ)   // 4096

typedef __half fp16;

// ---------------------------------------------------------------------------
// Scratch (allocation-free rule: __device__ globals)
// Activation splits: [rows][2048] = [hi(1024) | lo(1024)] fp16.
// Q/V per-head concat: [rows][2048], head h at h*128: hi dk 0..63, lo 64..127.
// K single fp16: [rows][1024], head h at h*64.
// Weights rounded fp16: wqkv [3072][1024] (W_Q pre-scaled by 0.125*log2e),
// wos [1024][1024].
// ---------------------------------------------------------------------------
__device__ fp16 g_xs  [MROWS * 2048];
__device__ fp16 g_wqkv[3 * DMODEL * DMODEL];
__device__ fp16 g_wos [DMODEL * DMODEL];
__device__ fp16 g_qs  [MROWS * 2048];
__device__ fp16 g_ks  [MROWS * 1024];
__device__ fp16 g_vs  [MROWS * 2048];
__device__ fp16 g_cs  [MROWS * 2048];

// ---------------------------------------------------------------------------
// PTX helpers (base compute_103 features only)
// ---------------------------------------------------------------------------
__device__ __forceinline__ uint32_t smem_u32(const void* p) {
    uint32_t a;
    asm("{ .reg .u64 t; cvta.to.shared.u64 t, %1; cvt.u32.u64 %0, t; }"
        : "=r"(a) : "l"(p));
    return a;
}
#define CP16(dst, src) \
    asm volatile("cp.async.cg.shared.global [%0], [%1], 16;" \
                 :: "r"(dst), "l"(src))
#define CP_COMMIT() asm volatile("cp.async.commit_group;" ::: "memory")
#define CP_WAIT0()  asm volatile("cp.async.wait_group 0;" ::: "memory")
#define CP_WAIT1()  asm volatile("cp.async.wait_group 1;" ::: "memory")

__device__ __forceinline__ void ldsm4(uint32_t addr, uint32_t& r0, uint32_t& r1,
                                      uint32_t& r2, uint32_t& r3) {
    asm volatile("ldmatrix.sync.aligned.m8n8.x4.shared.b16 {%0,%1,%2,%3}, [%4];"
                 : "=r"(r0), "=r"(r1), "=r"(r2), "=r"(r3) : "r"(addr));
}
__device__ __forceinline__ void ldsm4t(uint32_t addr, uint32_t& r0, uint32_t& r1,
                                       uint32_t& r2, uint32_t& r3) {
    asm volatile("ldmatrix.sync.aligned.m8n8.x4.trans.shared.b16 {%0,%1,%2,%3}, [%4];"
                 : "=r"(r0), "=r"(r1), "=r"(r2), "=r"(r3) : "r"(addr));
}
// D += A*B  (m16n8k16, fp16 in, fp32 accum)
__device__ __forceinline__ void mma16816(float* c, uint32_t a0, uint32_t a1,
                                         uint32_t a2, uint32_t a3,
                                         uint32_t b0, uint32_t b1) {
    asm volatile(
        "mma.sync.aligned.m16n8k16.row.col.f32.f16.f16.f32 "
        "{%0,%1,%2,%3}, {%4,%5,%6,%7}, {%8,%9}, {%0,%1,%2,%3};"
        : "+f"(c[0]), "+f"(c[1]), "+f"(c[2]), "+f"(c[3])
        : "r"(a0), "r"(a1), "r"(a2), "r"(a3), "r"(b0), "r"(b1));
}
__device__ __forceinline__ uint32_t packh(float a, float b) {
    __half2 t = __floats2half2_rn(a, b);
    return *(uint32_t*)&t;
}
__device__ __forceinline__ float ex2(float x) {
    float y;
    asm("ex2.approx.f32 %0, %1;" : "=f"(y) : "f"(x));
    return y;
}

// ---------------------------------------------------------------------------
// fp32 [R][1024] -> fp16 split [R][2048] = [hi | lo]
// ---------------------------------------------------------------------------
__device__ __forceinline__ void split_body(const float* __restrict__ in,
                                           fp16* __restrict__ out, int i) {
    float4 v = ((const float4*)in)[i];
    int r = i >> 8;
    int c = (i & 255) * 4;
    fp16 h0 = __float2half_rn(v.x), h1 = __float2half_rn(v.y);
    fp16 h2 = __float2half_rn(v.z), h3 = __float2half_rn(v.w);
    uint32_t* oh = (uint32_t*)(out + (size_t)r * 2048 + c);
    uint32_t* ol = (uint32_t*)(out + (size_t)r * 2048 + 1024 + c);
    oh[0] = packh(__half2float(h0), __half2float(h1));
    oh[1] = packh(__half2float(h2), __half2float(h3));
    ol[0] = packh(v.x - __half2float(h0), v.y - __half2float(h1));
    ol[1] = packh(v.z - __half2float(h2), v.w - __half2float(h3));
}

__global__ __launch_bounds__(256)
void split_kernel(const float* __restrict__ in, fp16* __restrict__ out, int n4) {
    int i = blockIdx.x * blockDim.x + threadIdx.x;
    if (i >= n4) return;
    split_body(in, out, i);
}

// Round the 4 weight matrices to plain fp16 [N][1024] (blockIdx.y selects).
// W_Q (y==0) is pre-scaled by 0.125*log2(e) so attention scores come out in
// log2 units, pre-multiplied by the softmax scale.
__global__ __launch_bounds__(256)
void round_w4(const float* __restrict__ w0, const float* __restrict__ w1,
              const float* __restrict__ w2, const float* __restrict__ w3,
              fp16* __restrict__ wqkv, fp16* __restrict__ wos, int n4) {
    int i = blockIdx.x * blockDim.x + threadIdx.x;
    if (i >= n4) return;
    int y = blockIdx.y;
    const float* src = (y == 0) ? w0 : (y == 1) ? w1 : (y == 2) ? w2 : w3;
    fp16* dst = (y < 3) ? wqkv + (size_t)y * DMODEL * DMODEL : wos;
    float s = (y == 0) ? 0.18033688f : 1.0f;   // 0.125 * log2(e)
    float4 v = ((const float4*)src)[i];
    uint32_t* o = (uint32_t*)(dst + (size_t)i * 4);
    o[0] = packh(v.x * s, v.y * s);
    o[1] = packh(v.z * s, v.w * s);
}

// ---------------------------------------------------------------------------
// Tensor-core GEMM: C[m][n] = (Ah + Al) . Bh   (fp16 2-term, K' = 2048)
//   chunks c: 0-15 -> Ah (A cols c*64), 16-31 -> Al (A cols 1024+(c-16)*64)
//   B col = (c & 15) * 64 in [N][1024].
// CTA tile 128(M) x 256(N), 512 thr, 16 warps (2x8), warp tile 64x32.
// 3-stage cp.async ring, one __syncthreads per chunk. 4 warps/SMSP.
// EPI 0: writes q (split), k (rounded), v (split) selected by n.
// EPI 1: fp32 + bias.
// ---------------------------------------------------------------------------
#define G_STRIDE 144                    // bytes per smem row (128B data + pad)
#define G_ASTG   (128 * G_STRIDE)       // 18432
#define G_BSTG   (256 * G_STRIDE)       // 36864
#define G_STAGE  (G_ASTG + G_BSTG)      // 55296
#define G_SMEM   (3 * G_STAGE)          // 165888
#define NCHUNK 32

__device__ __forceinline__ void gemm_prefetch(const fp16* A, const fp16* B,
                                              int m0, int n0, int c,
                                              uint32_t stg, int tid) {
    int ac = (c < 16) ? c * 64 : 1024 + (c - 16) * 64;
    int bc = (c & 15) * 64;
    const uint32_t sa = stg;
    const uint32_t sb = stg + G_ASTG;
#pragma unroll
    for (int it = 0; it < 2; it++) {
        int idx = tid + it * 512;          // 0..1023
        int row = idx >> 3, seg = idx & 7;
        CP16(sa + row * G_STRIDE + seg * 16,
             A + (size_t)(m0 + row) * 2048 + ac + seg * 8);
    }
#pragma unroll
    for (int it = 0; it < 4; it++) {
        int idx = tid + it * 512;          // 0..2047
        int row = idx >> 3, seg = idx & 7;
        CP16(sb + row * G_STRIDE + seg * 16,
             B + (size_t)(n0 + row) * 1024 + bc + seg * 8);
    }
}

template <int EPI>
__global__ __launch_bounds__(512, 1)
void mma_gemm(const fp16* __restrict__ A, const fp16* __restrict__ B,
              float* __restrict__ Cf,
              fp16* __restrict__ Cq, fp16* __restrict__ Ck, fp16* __restrict__ Cv,
              const float* __restrict__ bias) {
    extern __shared__ char smem[];
    const uint32_t sbase = smem_u32(smem);
    const int tid = threadIdx.x;
    const int w = tid >> 5, L = tid & 31;
    const int g = L >> 2, cq = L & 3;
    const int wm = w >> 3, wn = w & 7;       // 2 x 8 warp grid
    const int m0 = blockIdx.y * 128, n0 = blockIdx.x * 256;
    const int quad = L >> 3, l8 = L & 7;

    float acc[4][4][4];                       // 64 fp32 per thread
#pragma unroll
    for (int i = 0; i < 4; i++)
#pragma unroll
        for (int j = 0; j < 4; j++)
#pragma unroll
            for (int k = 0; k < 4; k++) acc[i][j][k] = 0.0f;

    gemm_prefetch(A, B, m0, n0, 0, sbase, tid);
    CP_COMMIT();
    gemm_prefetch(A, B, m0, n0, 1, sbase + G_STAGE, tid);
    CP_COMMIT();

    int stage = 0;
    for (int c = 0; c < NCHUNK; c++) {
        if (c == NCHUNK - 1) { CP_WAIT0(); } else { CP_WAIT1(); }
        __syncthreads();
        if (c + 2 < NCHUNK) {
            int s2 = stage + 2; if (s2 >= 3) s2 -= 3;
            gemm_prefetch(A, B, m0, n0, c + 2, sbase + s2 * G_STAGE, tid);
            CP_COMMIT();
        }
        const uint32_t sa = sbase + stage * G_STAGE;
        const uint32_t sb = sa + G_ASTG;

#pragma unroll
        for (int ks = 0; ks < 4; ks++) {
            uint32_t af[4][4];
#pragma unroll
            for (int i = 0; i < 4; i++) {
                int r = wm * 64 + i * 16 + (quad & 1) * 8 + l8;
                int kof = ks * 16 + (quad >> 1) * 8;
                ldsm4(sa + r * G_STRIDE + kof * 2,
                      af[i][0], af[i][1], af[i][2], af[i][3]);
            }
            uint32_t bfr[2][4];
#pragma unroll
            for (int p = 0; p < 2; p++) {
                int nr = wn * 32 + p * 16 + (quad >> 1) * 8 + l8;
                int kof = ks * 16 + (quad & 1) * 8;
                ldsm4(sb + nr * G_STRIDE + kof * 2,
                      bfr[p][0], bfr[p][1], bfr[p][2], bfr[p][3]);
            }
#pragma unroll
            for (int i = 0; i < 4; i++)
#pragma unroll
                for (int p = 0; p < 2; p++) {
                    mma16816(acc[i][2 * p], af[i][0], af[i][1], af[i][2], af[i][3],
                             bfr[p][0], bfr[p][1]);
                    mma16816(acc[i][2 * p + 1], af[i][0], af[i][1], af[i][2], af[i][3],
                             bfr[p][2], bfr[p][3]);
                }
        }
        stage++; if (stage == 3) stage = 0;
    }

    // Epilogue
#pragma unroll
    for (int i = 0; i < 4; i++) {
        int r0 = m0 + wm * 64 + i * 16 + g;
        int r1 = r0 + 8;
#pragma unroll
        for (int j = 0; j < 4; j++) {
            int col = n0 + wn * 32 + j * 8 + 2 * cq;
            float v0 = acc[i][j][0], v1 = acc[i][j][1];
            float v2 = acc[i][j][2], v3 = acc[i][j][3];
            if (EPI == 1) {
                float b0 = bias[col], b1 = bias[col + 1];
                *(float2*)(Cf + (size_t)r0 * 1024 + col) = make_float2(v0 + b0, v1 + b1);
                *(float2*)(Cf + (size_t)r1 * 1024 + col) = make_float2(v2 + b0, v3 + b1);
            } else {
                int mat = col >> 10, cc = col & 1023;
                int head = cc >> 6, dk = cc & 63;
                if (mat == 1) {
                    // K: single rounded fp16 [rows][1024]
                    size_t o0 = (size_t)r0 * 1024 + head * 64 + dk;
                    size_t o1 = (size_t)r1 * 1024 + head * 64 + dk;
                    *(uint32_t*)(Ck + o0) = packh(v0, v1);
                    *(uint32_t*)(Ck + o1) = packh(v2, v3);
                } else {
                    fp16* Cb = (mat == 0) ? Cq : Cv;
                    size_t o0 = (size_t)r0 * 2048 + head * 128 + dk;
                    size_t o1 = (size_t)r1 * 2048 + head * 128 + dk;
                    fp16 h0 = __float2half_rn(v0), h1 = __float2half_rn(v1);
                    fp16 h2 = __float2half_rn(v2), h3 = __float2half_rn(v3);
                    *(uint32_t*)(Cb + o0) = packh(__half2float(h0), __half2float(h1));
                    *(uint32_t*)(Cb + o0 + 64) = packh(v0 - __half2float(h0),
                                                       v1 - __half2float(h1));
                    *(uint32_t*)(Cb + o1) = packh(__half2float(h2), __half2float(h3));
                    *(uint32_t*)(Cb + o1 + 64) = packh(v2 - __half2float(h2),
                                                       v3 - __half2float(h3));
                }
            }
        }
    }
}

// ---------------------------------------------------------------------------
// Tensor-core flash attention, fp16 2-term, log2-domain softmax.
// Scores arrive pre-scaled by 0.125*log2(e) (folded into W_Q), so
// P = ex2(s - max) directly — single MUFU per probability.
// Grid (32 qblocks, 32 bh). CTA = 128 thr = 4 warps; warp owns 16 query rows.
// ---------------------------------------------------------------------------
#define K_STRIDE 144                  // 64 fp16 per key row + pad
#define V_STRIDE 272                  // 128 fp16 (vh|vl) per key row + pad
#define K_TILE   (64 * K_STRIDE)      // 9216
#define V_TILE   (64 * V_STRIDE)      // 17408
#define A_STAGE  (K_TILE + V_TILE)    // 26624
#define A_PAD_OFF (2 * A_STAGE)       // 53248
#define A_SMEM   (A_PAD_OFF + 512)    // 53760

__device__ __forceinline__ void attn_prefetch(const fp16* KS, const fp16* VS,
                                              const int* amask, char* smem,
                                              uint32_t sbase, int b, int h,
                                              int kt, int st, int tid) {
    const uint32_t kb = sbase + st * A_STAGE;
    const uint32_t vb = kb + K_TILE;
    const fp16* ksrc = KS + ((size_t)(b * NSEQ + kt)) * 1024 + h * 64;
    const fp16* vsrc = VS + ((size_t)(b * NSEQ + kt)) * 2048 + h * 128;
#pragma unroll
    for (int it = 0; it < 4; it++) {
        int idx = tid + it * 128;
        int row = idx >> 3, seg = idx & 7;
        CP16(kb + row * K_STRIDE + seg * 16, ksrc + (size_t)row * 1024 + seg * 8);
    }
#pragma unroll
    for (int it = 0; it < 8; it++) {
        int idx = tid + it * 128;
        int row = idx >> 4, seg = idx & 15;
        CP16(vb + row * V_STRIDE + seg * 16, vsrc + (size_t)row * 2048 + seg * 8);
    }
    if (tid < 64) {
        float pv = amask[b * NSEQ + kt + tid] ? 0.0f : -1e30f;
        *(float*)(smem + A_PAD_OFF + st * 256 + tid * 4) = pv;
    }
}

__global__ __launch_bounds__(128, 4)
void attn_mma(const fp16* __restrict__ QS, const fp16* __restrict__ KS,
              const fp16* __restrict__ VS, const int* __restrict__ amask,
              fp16* __restrict__ CS) {
    extern __shared__ char smem[];
    const uint32_t sbase = smem_u32(smem);
    const int tid = threadIdx.x;
    const int w = tid >> 5, L = tid & 31;
    const int g = L >> 2, cq = L & 3;
    const int quad = L >> 3, l8 = L & 7;
    const int qb = 31 - blockIdx.x;          // big blocks first
    const int m0 = qb * 64;
    const int bh = blockIdx.y;
    const int b = bh >> 4, h = bh & 15;
    const int rowA = m0 + w * 16 + g;
    const int rowB = rowA + 8;

    // Q fragments: qa[0..3] = qh k-steps, qa[4..7] = ql k-steps
    uint32_t qa[8][4];
    {
        const fp16* qA = QS + (size_t)(b * NSEQ + rowA) * 2048 + h * 128;
        const fp16* qB = QS + (size_t)(b * NSEQ + rowB) * 2048 + h * 128;
#pragma unroll
        for (int s = 0; s < 8; s++) {
            qa[s][0] = *(const uint32_t*)(qA + s * 16 + 2 * cq);
            qa[s][1] = *(const uint32_t*)(qB + s * 16 + 2 * cq);
            qa[s][2] = *(const uint32_t*)(qA + s * 16 + 2 * cq + 8);
            qa[s][3] = *(const uint32_t*)(qB + s * 16 + 2 * cq + 8);
        }
    }

    float co[8][4];
#pragma unroll
    for (int d = 0; d < 8; d++)
#pragma unroll
        for (int k = 0; k < 4; k++) co[d][k] = 0.0f;
    float mx0 = -1e30f, mx1 = -1e30f;
    float l0 = 0.0f, l1 = 0.0f;

    const int nt = qb + 1;
    attn_prefetch(KS, VS, amask, smem, sbase, b, h, 0, 0, tid);
    CP_COMMIT();

    for (int t = 0; t < nt; t++) {
        const int kt = t * 64;
        const int st = t & 1;
        CP_WAIT0();
        __syncthreads();
        if (t + 1 < nt) {
            attn_prefetch(KS, VS, amask, smem, sbase, b, h, (t + 1) * 64,
                          (t + 1) & 1, tid);
            CP_COMMIT();
        }

        const uint32_t kb = sbase + st * A_STAGE;
        const uint32_t vb = kb + K_TILE;
        const float* padf = (const float*)(smem + A_PAD_OFF + st * 256);

        // ---- scores: (qh + ql) x Kh, K fragments loaded once ----
        float sc[8][4];
#pragma unroll
        for (int f = 0; f < 8; f++)
#pragma unroll
            for (int k = 0; k < 4; k++) sc[f][k] = 0.0f;

#pragma unroll
        for (int ks = 0; ks < 4; ks++) {
            const int kof = ks * 16 + (quad & 1) * 8;
#pragma unroll
            for (int p = 0; p < 4; p++) {
                uint32_t b0, b1, b2, b3;
                int krow = p * 16 + (quad >> 1) * 8 + l8;
                ldsm4(kb + krow * K_STRIDE + kof * 2, b0, b1, b2, b3);
                mma16816(sc[2 * p], qa[ks][0], qa[ks][1], qa[ks][2], qa[ks][3], b0, b1);
                mma16816(sc[2 * p + 1], qa[ks][0], qa[ks][1], qa[ks][2], qa[ks][3], b2, b3);
                mma16816(sc[2 * p], qa[ks + 4][0], qa[ks + 4][1], qa[ks + 4][2],
                         qa[ks + 4][3], b0, b1);
                mma16816(sc[2 * p + 1], qa[ks + 4][0], qa[ks + 4][1], qa[ks + 4][2],
                         qa[ks + 4][3], b2, b3);
            }
        }

        // ---- mask + row max (log2 domain, no scale mul) ----
        const bool diag = (kt == m0);
        float mn0 = mx0, mn1 = mx1;
#pragma unroll
        for (int f = 0; f < 8; f++) {
            float2 pd = *(const float2*)(padf + f * 8 + 2 * cq);
            int k0 = kt + f * 8 + 2 * cq;
            float s0 = sc[f][0] + pd.x;
            float s1 = sc[f][1] + pd.y;
            float s2 = sc[f][2] + pd.x;
            float s3 = sc[f][3] + pd.y;
            if (diag) {
                if (k0 > rowA) s0 = -1e30f;
                if (k0 + 1 > rowA) s1 = -1e30f;
                if (k0 > rowB) s2 = -1e30f;
                if (k0 + 1 > rowB) s3 = -1e30f;
            }
            sc[f][0] = s0; sc[f][1] = s1; sc[f][2] = s2; sc[f][3] = s3;
            mn0 = fmaxf(mn0, fmaxf(s0, s1));
            mn1 = fmaxf(mn1, fmaxf(s2, s3));
        }
        mn0 = fmaxf(mn0, __shfl_xor_sync(0xffffffffu, mn0, 1));
        mn0 = fmaxf(mn0, __shfl_xor_sync(0xffffffffu, mn0, 2));
        mn1 = fmaxf(mn1, __shfl_xor_sync(0xffffffffu, mn1, 1));
        mn1 = fmaxf(mn1, __shfl_xor_sync(0xffffffffu, mn1, 2));

        const float corr0 = ex2(mx0 - mn0);
        const float corr1 = ex2(mx1 - mn1);
        mx0 = mn0; mx1 = mn1;
        l0 *= corr0; l1 *= corr1;
#pragma unroll
        for (int d = 0; d < 8; d++) {
            co[d][0] *= corr0; co[d][1] *= corr0;
            co[d][2] *= corr1; co[d][3] *= corr1;
        }

        // ---- P = ex2(s - max), fp16 fragments ----
        uint32_t phA[8], phB[8];
#pragma unroll
        for (int f = 0; f < 8; f++) {
            float p0 = ex2(sc[f][0] - mn0), p1 = ex2(sc[f][1] - mn0);
            float p2 = ex2(sc[f][2] - mn1), p3 = ex2(sc[f][3] - mn1);
            l0 += p0 + p1; l1 += p2 + p3;
            phA[f] = packh(p0, p1);
            phB[f] = packh(p2, p3);
        }

        // ---- O += Ph @ (Vh + Vl) ----
#pragma unroll
        for (int kk = 0; kk < 4; kk++) {
            uint32_t a0 = phA[2 * kk], a1 = phB[2 * kk];
            uint32_t a2 = phA[2 * kk + 1], a3 = phB[2 * kk + 1];
#pragma unroll
            for (int dp = 0; dp < 4; dp++) {
                int key = kk * 16 + (quad & 1) * 8 + l8;
                int dkc = (2 * dp + (quad >> 1)) * 8;
                uint32_t vh0, vh1, vh2, vh3, vl0, vl1, vl2, vl3;
                ldsm4t(vb + key * V_STRIDE + dkc * 2, vh0, vh1, vh2, vh3);
                ldsm4t(vb + key * V_STRIDE + 128 + dkc * 2, vl0, vl1, vl2, vl3);
                mma16816(co[2 * dp],     a0, a1, a2, a3, vh0, vh1);
                mma16816(co[2 * dp + 1], a0, a1, a2, a3, vh2, vh3);
                mma16816(co[2 * dp],     a0, a1, a2, a3, vl0, vl1);
                mma16816(co[2 * dp + 1], a0, a1, a2, a3, vl2, vl3);
            }
        }
    }

    // ---- finalize ----
    l0 += __shfl_xor_sync(0xffffffffu, l0, 1);
    l0 += __shfl_xor_sync(0xffffffffu, l0, 2);
    l1 += __shfl_xor_sync(0xffffffffu, l1, 1);
    l1 += __shfl_xor_sync(0xffffffffu, l1, 2);
    const float inv0 = 1.0f / l0, inv1 = 1.0f / l1;

#pragma unroll
    for (int d = 0; d < 8; d++) {
        int dk = d * 8 + 2 * cq;
        size_t bA = (size_t)(b * NSEQ + rowA) * 2048 + h * 64 + dk;
        size_t bB = (size_t)(b * NSEQ + rowB) * 2048 + h * 64 + dk;
        float v0 = co[d][0] * inv0, v1 = co[d][1] * inv0;
        float v2 = co[d][2] * inv1, v3 = co[d][3] * inv1;
        fp16 h0 = __float2half_rn(v0), h1 = __float2half_rn(v1);
        fp16 h2 = __float2half_rn(v2), h3 = __float2half_rn(v3);
        *(uint32_t*)(CS + bA) = packh(__half2float(h0), __half2float(h1));
        *(uint32_t*)(CS + bA + 1024) = packh(v0 - __half2float(h0),
                                             v1 - __half2float(h1));
        *(uint32_t*)(CS + bB) = packh(__half2float(h2), __half2float(h3));
        *(uint32_t*)(CS + bB + 1024) = packh(v2 - __half2float(h2),
                                             v3 - __half2float(h3));
    }
}

// ---------------------------------------------------------------------------
// Launch
// ---------------------------------------------------------------------------
extern "C" void kernel_launch(void* const* d_in, const int* in_sizes, int n_in,
                              void* d_out, int out_size) {
    const float* x     = (const float*)d_in[0];
    const int*   amask = (const int*)d_in[1];
    const float* W_Q   = (const float*)d_in[2];
    const float* W_K   = (const float*)d_in[3];
    const float* W_V   = (const float*)d_in[4];
    const float* W_out = (const float*)d_in[5];
    const float* b_out = (const float*)d_in[6];
    float* out = (float*)d_out;

    fp16 *xs, *wqkv, *wos, *qs, *ks, *vs, *cs;
    cudaGetSymbolAddress((void**)&xs, g_xs);
    cudaGetSymbolAddress((void**)&wqkv, g_wqkv);
    cudaGetSymbolAddress((void**)&wos, g_wos);
    cudaGetSymbolAddress((void**)&qs, g_qs);
    cudaGetSymbolAddress((void**)&ks, g_ks);
    cudaGetSymbolAddress((void**)&vs, g_vs);
    cudaGetSymbolAddress((void**)&cs, g_cs);

    cudaFuncSetAttribute(mma_gemm<0>, cudaFuncAttributeMaxDynamicSharedMemorySize, G_SMEM);
    cudaFuncSetAttribute(mma_gemm<1>, cudaFuncAttributeMaxDynamicSharedMemorySize, G_SMEM);
    cudaFuncSetAttribute(attn_mma, cudaFuncAttributeMaxDynamicSharedMemorySize, A_SMEM);

    const int nx4 = MROWS * DMODEL / 4;
    const int nw4 = DMODEL * DMODEL / 4;
    split_kernel<<<(nx4 + 255) / 256, 256>>>(x, xs, nx4);
    dim3 wgrid((nw4 + 255) / 256, 4);
    round_w4<<<wgrid, 256>>>(W_Q, W_K, W_V, W_out, wqkv, wos, nw4);

    dim3 qkvgrid(3 * DMODEL / 256, MROWS / 128);   // (12, 32)
    mma_gemm<0><<<qkvgrid, 512, G_SMEM>>>(xs, wqkv, nullptr, qs, ks, vs, nullptr);

    dim3 agrid(NSEQ / 64, BATCH * NHEAD);          // (32, 32)
    attn_mma<<<agrid, 128, A_SMEM>>>(qs, ks, vs, amask, cs);

    dim3 ogrid(DMODEL / 256, MROWS / 128);         // (4, 32)
    mma_gemm<1><<<ogrid, 512, G_SMEM>>>(cs, wos, out, nullptr, nullptr, nullptr, b_out);
}

// round 12
// speedup vs baseline: 1.4791x; 1.4791x over previous
#include <cuda_runtime.h>
#include <cuda_fp16.h>
#include <cstdint>

// Problem constants
#define BATCH 2
#define NSEQ  2048
#define DMODEL 1024
#define NHEAD 16
#define DK    64
#define MROWS (BATCH * NSEQ)   // 4096

typedef __half fp16;

// ---------------------------------------------------------------------------
// Scratch (allocation-free rule: __device__ globals)
// xs, cs: single-term rounded fp16 [rows][1024].
// Q/V per-head concat split: [rows][2048], head h at h*128: hi 0..63, lo 64..127.
// K single fp16: [rows][1024], head h at h*64.
// Weights rounded fp16: wqkv [3072][1024] (W_Q pre-scaled by 0.125*log2e),
// wos [1024][1024].
// ---------------------------------------------------------------------------
__device__ fp16 g_xs  [MROWS * 1024];
__device__ fp16 g_wqkv[3 * DMODEL * DMODEL];
__device__ fp16 g_wos [DMODEL * DMODEL];
__device__ fp16 g_qs  [MROWS * 2048];
__device__ fp16 g_ks  [MROWS * 1024];
__device__ fp16 g_vs  [MROWS * 2048];
__device__ fp16 g_cs  [MROWS * 1024];

// ---------------------------------------------------------------------------
// PTX helpers (base compute_103 features only)
// ---------------------------------------------------------------------------
__device__ __forceinline__ uint32_t smem_u32(const void* p) {
    uint32_t a;
    asm("{ .reg .u64 t; cvta.to.shared.u64 t, %1; cvt.u32.u64 %0, t; }"
        : "=r"(a) : "l"(p));
    return a;
}
#define CP16(dst, src) \
    asm volatile("cp.async.cg.shared.global [%0], [%1], 16;" \
                 :: "r"(dst), "l"(src))
#define CP_COMMIT() asm volatile("cp.async.commit_group;" ::: "memory")
#define CP_WAIT0()  asm volatile("cp.async.wait_group 0;" ::: "memory")
#define CP_WAIT1()  asm volatile("cp.async.wait_group 1;" ::: "memory")

__device__ __forceinline__ void ldsm4(uint32_t addr, uint32_t& r0, uint32_t& r1,
                                      uint32_t& r2, uint32_t& r3) {
    asm volatile("ldmatrix.sync.aligned.m8n8.x4.shared.b16 {%0,%1,%2,%3}, [%4];"
                 : "=r"(r0), "=r"(r1), "=r"(r2), "=r"(r3) : "r"(addr));
}
__device__ __forceinline__ void ldsm4t(uint32_t addr, uint32_t& r0, uint32_t& r1,
                                       uint32_t& r2, uint32_t& r3) {
    asm volatile("ldmatrix.sync.aligned.m8n8.x4.trans.shared.b16 {%0,%1,%2,%3}, [%4];"
                 : "=r"(r0), "=r"(r1), "=r"(r2), "=r"(r3) : "r"(addr));
}
// D += A*B  (m16n8k16, fp16 in, fp32 accum)
__device__ __forceinline__ void mma16816(float* c, uint32_t a0, uint32_t a1,
                                         uint32_t a2, uint32_t a3,
                                         uint32_t b0, uint32_t b1) {
    asm volatile(
        "mma.sync.aligned.m16n8k16.row.col.f32.f16.f16.f32 "
        "{%0,%1,%2,%3}, {%4,%5,%6,%7}, {%8,%9}, {%0,%1,%2,%3};"
        : "+f"(c[0]), "+f"(c[1]), "+f"(c[2]), "+f"(c[3])
        : "r"(a0), "r"(a1), "r"(a2), "r"(a3), "r"(b0), "r"(b1));
}
__device__ __forceinline__ uint32_t packh(float a, float b) {
    __half2 t = __floats2half2_rn(a, b);
    return *(uint32_t*)&t;
}
__device__ __forceinline__ float ex2(float x) {
    float y;
    asm("ex2.approx.f32 %0, %1;" : "=f"(y) : "f"(x));
    return y;
}

// ---------------------------------------------------------------------------
// fp32 [R][1024] -> rounded fp16 [R][1024]
// ---------------------------------------------------------------------------
__global__ __launch_bounds__(256)
void round_kernel(const float* __restrict__ in, fp16* __restrict__ out, int n4) {
    int i = blockIdx.x * blockDim.x + threadIdx.x;
    if (i >= n4) return;
    float4 v = ((const float4*)in)[i];
    uint32_t* o = (uint32_t*)(out + (size_t)i * 4);
    o[0] = packh(v.x, v.y);
    o[1] = packh(v.z, v.w);
}

// Round the 4 weight matrices to fp16 [N][1024] (blockIdx.y selects).
// W_Q (y==0) pre-scaled by 0.125*log2(e): scores come out in log2 units.
__global__ __launch_bounds__(256)
void round_w4(const float* __restrict__ w0, const float* __restrict__ w1,
              const float* __restrict__ w2, const float* __restrict__ w3,
              fp16* __restrict__ wqkv, fp16* __restrict__ wos, int n4) {
    int i = blockIdx.x * blockDim.x + threadIdx.x;
    if (i >= n4) return;
    int y = blockIdx.y;
    const float* src = (y == 0) ? w0 : (y == 1) ? w1 : (y == 2) ? w2 : w3;
    fp16* dst = (y < 3) ? wqkv + (size_t)y * DMODEL * DMODEL : wos;
    float s = (y == 0) ? 0.18033688f : 1.0f;   // 0.125 * log2(e)
    float4 v = ((const float4*)src)[i];
    uint32_t* o = (uint32_t*)(dst + (size_t)i * 4);
    o[0] = packh(v.x * s, v.y * s);
    o[1] = packh(v.z * s, v.w * s);
}

// ---------------------------------------------------------------------------
// Tensor-core GEMM: C[m][n] = A . B, both fp16 single-term, K = 1024.
// A [rows][1024], B [NB][1024]. CTA tile 128x256, 512 thr, warp tile 64x32.
// 3-stage cp.async ring, one __syncthreads per chunk (16 chunks of K=64).
// EPI 0: writes q (split), k (rounded), v (split) selected by n.
// EPI 1: fp32 + bias.
// ---------------------------------------------------------------------------
#define G_STRIDE 144                    // bytes per smem row (128B data + pad)
#define G_ASTG   (128 * G_STRIDE)       // 18432
#define G_BSTG   (256 * G_STRIDE)       // 36864
#define G_STAGE  (G_ASTG + G_BSTG)      // 55296
#define G_SMEM   (3 * G_STAGE)          // 165888
#define NCHUNK 16

__device__ __forceinline__ void gemm_prefetch(const fp16* A, const fp16* B,
                                              int m0, int n0, int c,
                                              uint32_t stg, int tid) {
    int ac = c * 64;
    int bc = c * 64;
    const uint32_t sa = stg;
    const uint32_t sb = stg + G_ASTG;
#pragma unroll
    for (int it = 0; it < 2; it++) {
        int idx = tid + it * 512;          // 0..1023
        int row = idx >> 3, seg = idx & 7;
        CP16(sa + row * G_STRIDE + seg * 16,
             A + (size_t)(m0 + row) * 1024 + ac + seg * 8);
    }
#pragma unroll
    for (int it = 0; it < 4; it++) {
        int idx = tid + it * 512;          // 0..2047
        int row = idx >> 3, seg = idx & 7;
        CP16(sb + row * G_STRIDE + seg * 16,
             B + (size_t)(n0 + row) * 1024 + bc + seg * 8);
    }
}

template <int EPI>
__global__ __launch_bounds__(512, 1)
void mma_gemm(const fp16* __restrict__ A, const fp16* __restrict__ B,
              float* __restrict__ Cf,
              fp16* __restrict__ Cq, fp16* __restrict__ Ck, fp16* __restrict__ Cv,
              const float* __restrict__ bias) {
    extern __shared__ char smem[];
    const uint32_t sbase = smem_u32(smem);
    const int tid = threadIdx.x;
    const int w = tid >> 5, L = tid & 31;
    const int g = L >> 2, cq = L & 3;
    const int wm = w >> 3, wn = w & 7;       // 2 x 8 warp grid
    const int m0 = blockIdx.y * 128, n0 = blockIdx.x * 256;
    const int quad = L >> 3, l8 = L & 7;

    float acc[4][4][4];                       // 64 fp32 per thread
#pragma unroll
    for (int i = 0; i < 4; i++)
#pragma unroll
        for (int j = 0; j < 4; j++)
#pragma unroll
            for (int k = 0; k < 4; k++) acc[i][j][k] = 0.0f;

    gemm_prefetch(A, B, m0, n0, 0, sbase, tid);
    CP_COMMIT();
    gemm_prefetch(A, B, m0, n0, 1, sbase + G_STAGE, tid);
    CP_COMMIT();

    int stage = 0;
    for (int c = 0; c < NCHUNK; c++) {
        if (c == NCHUNK - 1) { CP_WAIT0(); } else { CP_WAIT1(); }
        __syncthreads();
        if (c + 2 < NCHUNK) {
            int s2 = stage + 2; if (s2 >= 3) s2 -= 3;
            gemm_prefetch(A, B, m0, n0, c + 2, sbase + s2 * G_STAGE, tid);
            CP_COMMIT();
        }
        const uint32_t sa = sbase + stage * G_STAGE;
        const uint32_t sb = sa + G_ASTG;

#pragma unroll
        for (int ks = 0; ks < 4; ks++) {
            uint32_t af[4][4];
#pragma unroll
            for (int i = 0; i < 4; i++) {
                int r = wm * 64 + i * 16 + (quad & 1) * 8 + l8;
                int kof = ks * 16 + (quad >> 1) * 8;
                ldsm4(sa + r * G_STRIDE + kof * 2,
                      af[i][0], af[i][1], af[i][2], af[i][3]);
            }
            uint32_t bfr[2][4];
#pragma unroll
            for (int p = 0; p < 2; p++) {
                int nr = wn * 32 + p * 16 + (quad >> 1) * 8 + l8;
                int kof = ks * 16 + (quad & 1) * 8;
                ldsm4(sb + nr * G_STRIDE + kof * 2,
                      bfr[p][0], bfr[p][1], bfr[p][2], bfr[p][3]);
            }
#pragma unroll
            for (int i = 0; i < 4; i++)
#pragma unroll
                for (int p = 0; p < 2; p++) {
                    mma16816(acc[i][2 * p], af[i][0], af[i][1], af[i][2], af[i][3],
                             bfr[p][0], bfr[p][1]);
                    mma16816(acc[i][2 * p + 1], af[i][0], af[i][1], af[i][2], af[i][3],
                             bfr[p][2], bfr[p][3]);
                }
        }
        stage++; if (stage == 3) stage = 0;
    }

    // Epilogue
#pragma unroll
    for (int i = 0; i < 4; i++) {
        int r0 = m0 + wm * 64 + i * 16 + g;
        int r1 = r0 + 8;
#pragma unroll
        for (int j = 0; j < 4; j++) {
            int col = n0 + wn * 32 + j * 8 + 2 * cq;
            float v0 = acc[i][j][0], v1 = acc[i][j][1];
            float v2 = acc[i][j][2], v3 = acc[i][j][3];
            if (EPI == 1) {
                float b0 = bias[col], b1 = bias[col + 1];
                *(float2*)(Cf + (size_t)r0 * 1024 + col) = make_float2(v0 + b0, v1 + b1);
                *(float2*)(Cf + (size_t)r1 * 1024 + col) = make_float2(v2 + b0, v3 + b1);
            } else {
                int mat = col >> 10, cc = col & 1023;
                int head = cc >> 6, dk = cc & 63;
                if (mat == 1) {
                    // K: single rounded fp16 [rows][1024]
                    size_t o0 = (size_t)r0 * 1024 + head * 64 + dk;
                    size_t o1 = (size_t)r1 * 1024 + head * 64 + dk;
                    *(uint32_t*)(Ck + o0) = packh(v0, v1);
                    *(uint32_t*)(Ck + o1) = packh(v2, v3);
                } else {
                    fp16* Cb = (mat == 0) ? Cq : Cv;
                    size_t o0 = (size_t)r0 * 2048 + head * 128 + dk;
                    size_t o1 = (size_t)r1 * 2048 + head * 128 + dk;
                    fp16 h0 = __float2half_rn(v0), h1 = __float2half_rn(v1);
                    fp16 h2 = __float2half_rn(v2), h3 = __float2half_rn(v3);
                    *(uint32_t*)(Cb + o0) = packh(__half2float(h0), __half2float(h1));
                    *(uint32_t*)(Cb + o0 + 64) = packh(v0 - __half2float(h0),
                                                       v1 - __half2float(h1));
                    *(uint32_t*)(Cb + o1) = packh(__half2float(h2), __half2float(h3));
                    *(uint32_t*)(Cb + o1 + 64) = packh(v2 - __half2float(h2),
                                                       v3 - __half2float(h3));
                }
            }
        }
    }
}

// ---------------------------------------------------------------------------
// Tensor-core flash attention, fp16, log2-domain softmax.
// Load-balanced: CTA p handles q-blocks (31-p) then (p): 33 tiles each,
// grid (16, 32) = 512 CTAs -> one balanced wave at 4 CTA/SM.
// l accumulated via ones-MMA (exact f32 sum of the fp16 P used in PV).
// Fully-padded KV tiles skipped (attention_mask is monotone).
// ---------------------------------------------------------------------------
#define K_STRIDE 144                  // 64 fp16 per key row + pad
#define V_STRIDE 272                  // 128 fp16 (vh|vl) per key row + pad
#define K_TILE   (64 * K_STRIDE)      // 9216
#define V_TILE   (64 * V_STRIDE)      // 17408
#define A_STAGE  (K_TILE + V_TILE)    // 26624
#define A_PAD_OFF (2 * A_STAGE)       // 53248
#define A_SMEM   (A_PAD_OFF + 512)    // 53760
#define HONES 0x3C003C00u             // (1.0h, 1.0h)

__device__ __forceinline__ void attn_prefetch(const fp16* KS, const fp16* VS,
                                              const int* amask, char* smem,
                                              uint32_t sbase, int b, int h,
                                              int kt, int st, int tid) {
    const uint32_t kb = sbase + st * A_STAGE;
    const uint32_t vb = kb + K_TILE;
    const fp16* ksrc = KS + ((size_t)(b * NSEQ + kt)) * 1024 + h * 64;
    const fp16* vsrc = VS + ((size_t)(b * NSEQ + kt)) * 2048 + h * 128;
#pragma unroll
    for (int it = 0; it < 4; it++) {
        int idx = tid + it * 128;
        int row = idx >> 3, seg = idx & 7;
        CP16(kb + row * K_STRIDE + seg * 16, ksrc + (size_t)row * 1024 + seg * 8);
    }
#pragma unroll
    for (int it = 0; it < 8; it++) {
        int idx = tid + it * 128;
        int row = idx >> 4, seg = idx & 15;
        CP16(vb + row * V_STRIDE + seg * 16, vsrc + (size_t)row * 2048 + seg * 8);
    }
    if (tid < 64) {
        float pv = amask[b * NSEQ + kt + tid] ? 0.0f : -1e30f;
        *(float*)(smem + A_PAD_OFF + st * 256 + tid * 4) = pv;
    }
}

__global__ __launch_bounds__(128, 4)
void attn_mma(const fp16* __restrict__ QS, const fp16* __restrict__ KS,
              const fp16* __restrict__ VS, const int* __restrict__ amask,
              fp16* __restrict__ CS) {
    extern __shared__ char smem[];
    const uint32_t sbase = smem_u32(smem);
    const int tid = threadIdx.x;
    const int w = tid >> 5, L = tid & 31;
    const int g = L >> 2, cq = L & 3;
    const int quad = L >> 3, l8 = L & 7;
    const int pr = blockIdx.x;               // 0..15
    const int bh = blockIdx.y;
    const int b = bh >> 4, h = bh & 15;

    for (int seg = 0; seg < 2; seg++) {
        const int qb = (seg == 0) ? (31 - pr) : pr;
        const int m0 = qb * 64;
        const int rowA = m0 + w * 16 + g;
        const int rowB = rowA + 8;

        // Q fragments: qa[0..3] = qh k-steps, qa[4..7] = ql k-steps
        uint32_t qa[8][4];
        {
            const fp16* qA = QS + (size_t)(b * NSEQ + rowA) * 2048 + h * 128;
            const fp16* qB = QS + (size_t)(b * NSEQ + rowB) * 2048 + h * 128;
#pragma unroll
            for (int s = 0; s < 8; s++) {
                qa[s][0] = *(const uint32_t*)(qA + s * 16 + 2 * cq);
                qa[s][1] = *(const uint32_t*)(qB + s * 16 + 2 * cq);
                qa[s][2] = *(const uint32_t*)(qA + s * 16 + 2 * cq + 8);
                qa[s][3] = *(const uint32_t*)(qB + s * 16 + 2 * cq + 8);
            }
        }

        float co[8][4];
#pragma unroll
        for (int d = 0; d < 8; d++)
#pragma unroll
            for (int k = 0; k < 4; k++) co[d][k] = 0.0f;
        float lacc[4] = {0.0f, 0.0f, 0.0f, 0.0f};
        float mx0 = -1e30f, mx1 = -1e30f;

        const int nt = qb + 1;
        __syncthreads();   // smem stage reuse across segments
        attn_prefetch(KS, VS, amask, smem, sbase, b, h, 0, 0, tid);
        CP_COMMIT();

        for (int t = 0; t < nt; t++) {
            const int kt = t * 64;
            const int st = t & 1;
            CP_WAIT0();
            __syncthreads();
            if (t + 1 < nt) {
                attn_prefetch(KS, VS, amask, smem, sbase, b, h, (t + 1) * 64,
                              (t + 1) & 1, tid);
                CP_COMMIT();
            }

            const uint32_t kb = sbase + st * A_STAGE;
            const uint32_t vb = kb + K_TILE;
            const float* padf = (const float*)(smem + A_PAD_OFF + st * 256);

            // Fully-padded tile (mask monotone): nothing to do.
            if (padf[0] < -1e29f) continue;

            // ---- scores: (qh + ql) x Kh, K fragments loaded once ----
            float sc[8][4];
#pragma unroll
            for (int f = 0; f < 8; f++)
#pragma unroll
                for (int k = 0; k < 4; k++) sc[f][k] = 0.0f;

#pragma unroll
            for (int ks = 0; ks < 4; ks++) {
                const int kof = ks * 16 + (quad & 1) * 8;
#pragma unroll
                for (int p = 0; p < 4; p++) {
                    uint32_t b0, b1, b2, b3;
                    int krow = p * 16 + (quad >> 1) * 8 + l8;
                    ldsm4(kb + krow * K_STRIDE + kof * 2, b0, b1, b2, b3);
                    mma16816(sc[2 * p], qa[ks][0], qa[ks][1], qa[ks][2], qa[ks][3],
                             b0, b1);
                    mma16816(sc[2 * p + 1], qa[ks][0], qa[ks][1], qa[ks][2], qa[ks][3],
                             b2, b3);
                    mma16816(sc[2 * p], qa[ks + 4][0], qa[ks + 4][1], qa[ks + 4][2],
                             qa[ks + 4][3], b0, b1);
                    mma16816(sc[2 * p + 1], qa[ks + 4][0], qa[ks + 4][1], qa[ks + 4][2],
                             qa[ks + 4][3], b2, b3);
                }
            }

            // ---- mask + row max (log2 domain) ----
            const bool diag = (kt == m0);
            float mn0 = mx0, mn1 = mx1;
#pragma unroll
            for (int f = 0; f < 8; f++) {
                float2 pd = *(const float2*)(padf + f * 8 + 2 * cq);
                int k0 = kt + f * 8 + 2 * cq;
                float s0 = sc[f][0] + pd.x;
                float s1 = sc[f][1] + pd.y;
                float s2 = sc[f][2] + pd.x;
                float s3 = sc[f][3] + pd.y;
                if (diag) {
                    if (k0 > rowA) s0 = -1e30f;
                    if (k0 + 1 > rowA) s1 = -1e30f;
                    if (k0 > rowB) s2 = -1e30f;
                    if (k0 + 1 > rowB) s3 = -1e30f;
                }
                sc[f][0] = s0; sc[f][1] = s1; sc[f][2] = s2; sc[f][3] = s3;
                mn0 = fmaxf(mn0, fmaxf(s0, s1));
                mn1 = fmaxf(mn1, fmaxf(s2, s3));
            }
            mn0 = fmaxf(mn0, __shfl_xor_sync(0xffffffffu, mn0, 1));
            mn0 = fmaxf(mn0, __shfl_xor_sync(0xffffffffu, mn0, 2));
            mn1 = fmaxf(mn1, __shfl_xor_sync(0xffffffffu, mn1, 1));
            mn1 = fmaxf(mn1, __shfl_xor_sync(0xffffffffu, mn1, 2));

            const float corr0 = ex2(mx0 - mn0);
            const float corr1 = ex2(mx1 - mn1);
            mx0 = mn0; mx1 = mn1;
#pragma unroll
            for (int d = 0; d < 8; d++) {
                co[d][0] *= corr0; co[d][1] *= corr0;
                co[d][2] *= corr1; co[d][3] *= corr1;
            }
            lacc[0] *= corr0; lacc[1] *= corr0;
            lacc[2] *= corr1; lacc[3] *= corr1;

            // ---- P = ex2(s - max), fp16 fragments ----
            uint32_t phA[8], phB[8];
#pragma unroll
            for (int f = 0; f < 8; f++) {
                float p0 = ex2(sc[f][0] - mn0), p1 = ex2(sc[f][1] - mn0);
                float p2 = ex2(sc[f][2] - mn1), p3 = ex2(sc[f][3] - mn1);
                phA[f] = packh(p0, p1);
                phB[f] = packh(p2, p3);
            }

            // ---- l += P @ ones (exact f32 row sums of fp16 P) ----
#pragma unroll
            for (int kk = 0; kk < 4; kk++)
                mma16816(lacc, phA[2 * kk], phB[2 * kk],
                         phA[2 * kk + 1], phB[2 * kk + 1], HONES, HONES);

            // ---- O += Ph @ (Vh + Vl) ----
#pragma unroll
            for (int kk = 0; kk < 4; kk++) {
                uint32_t a0 = phA[2 * kk], a1 = phB[2 * kk];
                uint32_t a2 = phA[2 * kk + 1], a3 = phB[2 * kk + 1];
#pragma unroll
                for (int dp = 0; dp < 4; dp++) {
                    int key = kk * 16 + (quad & 1) * 8 + l8;
                    int dkc = (2 * dp + (quad >> 1)) * 8;
                    uint32_t vh0, vh1, vh2, vh3, vl0, vl1, vl2, vl3;
                    ldsm4t(vb + key * V_STRIDE + dkc * 2, vh0, vh1, vh2, vh3);
                    ldsm4t(vb + key * V_STRIDE + 128 + dkc * 2, vl0, vl1, vl2, vl3);
                    mma16816(co[2 * dp],     a0, a1, a2, a3, vh0, vh1);
                    mma16816(co[2 * dp + 1], a0, a1, a2, a3, vh2, vh3);
                    mma16816(co[2 * dp],     a0, a1, a2, a3, vl0, vl1);
                    mma16816(co[2 * dp + 1], a0, a1, a2, a3, vl2, vl3);
                }
            }
        }

        // ---- finalize: l already in lacc[0] (rowA) / lacc[2] (rowB) ----
        const float inv0 = 1.0f / lacc[0], inv1 = 1.0f / lacc[2];
#pragma unroll
        for (int d = 0; d < 8; d++) {
            int dk = d * 8 + 2 * cq;
            size_t bA = (size_t)(b * NSEQ + rowA) * 1024 + h * 64 + dk;
            size_t bB = (size_t)(b * NSEQ + rowB) * 1024 + h * 64 + dk;
            *(uint32_t*)(CS + bA) = packh(co[d][0] * inv0, co[d][1] * inv0);
            *(uint32_t*)(CS + bB) = packh(co[d][2] * inv1, co[d][3] * inv1);
        }
    }
}

// ---------------------------------------------------------------------------
// Launch
// ---------------------------------------------------------------------------
extern "C" void kernel_launch(void* const* d_in, const int* in_sizes, int n_in,
                              void* d_out, int out_size) {
    const float* x     = (const float*)d_in[0];
    const int*   amask = (const int*)d_in[1];
    const float* W_Q   = (const float*)d_in[2];
    const float* W_K   = (const float*)d_in[3];
    const float* W_V   = (const float*)d_in[4];
    const float* W_out = (const float*)d_in[5];
    const float* b_out = (const float*)d_in[6];
    float* out = (float*)d_out;

    fp16 *xs, *wqkv, *wos, *qs, *ks, *vs, *cs;
    cudaGetSymbolAddress((void**)&xs, g_xs);
    cudaGetSymbolAddress((void**)&wqkv, g_wqkv);
    cudaGetSymbolAddress((void**)&wos, g_wos);
    cudaGetSymbolAddress((void**)&qs, g_qs);
    cudaGetSymbolAddress((void**)&ks, g_ks);
    cudaGetSymbolAddress((void**)&vs, g_vs);
    cudaGetSymbolAddress((void**)&cs, g_cs);

    cudaFuncSetAttribute(mma_gemm<0>, cudaFuncAttributeMaxDynamicSharedMemorySize, G_SMEM);
    cudaFuncSetAttribute(mma_gemm<1>, cudaFuncAttributeMaxDynamicSharedMemorySize, G_SMEM);
    cudaFuncSetAttribute(attn_mma, cudaFuncAttributeMaxDynamicSharedMemorySize, A_SMEM);

    const int nx4 = MROWS * DMODEL / 4;
    const int nw4 = DMODEL * DMODEL / 4;
    round_kernel<<<(nx4 + 255) / 256, 256>>>(x, xs, nx4);
    dim3 wgrid((nw4 + 255) / 256, 4);
    round_w4<<<wgrid, 256>>>(W_Q, W_K, W_V, W_out, wqkv, wos, nw4);

    dim3 qkvgrid(3 * DMODEL / 256, MROWS / 128);   // (12, 32)
    mma_gemm<0><<<qkvgrid, 512, G_SMEM>>>(xs, wqkv, nullptr, qs, ks, vs, nullptr);

    dim3 agrid(16, BATCH * NHEAD);                 // (16, 32) balanced pairs
    attn_mma<<<agrid, 128, A_SMEM>>>(qs, ks, vs, amask, cs);

    dim3 ogrid(DMODEL / 256, MROWS / 128);         // (4, 32)
    mma_gemm<1><<<ogrid, 512, G_SMEM>>>(cs, wos, out, nullptr, nullptr, nullptr, b_out);
}

// round 13
// speedup vs baseline: 1.8624x; 1.2592x over previous
#include <cuda_runtime.h>
#include <cuda_fp16.h>
#include <cstdint>

// Problem constants
#define BATCH 2
#define NSEQ  2048
#define DMODEL 1024
#define NHEAD 16
#define DK    64
#define MROWS (BATCH * NSEQ)   // 4096

typedef __half fp16;

// ---------------------------------------------------------------------------
// Scratch (allocation-free rule: __device__ globals)
// All activations single rounded fp16 [rows][1024].
// q/k/v: per-head layout == natural GEMM output layout (head h at h*64).
// Weights rounded fp16: wqkv [3072][1024] (W_Q pre-scaled by 0.125*log2e),
// wos [1024][1024].
// ---------------------------------------------------------------------------
__device__ fp16 g_xs  [MROWS * 1024];
__device__ fp16 g_wqkv[3 * DMODEL * DMODEL];
__device__ fp16 g_wos [DMODEL * DMODEL];
__device__ fp16 g_qs  [MROWS * 1024];
__device__ fp16 g_ks  [MROWS * 1024];
__device__ fp16 g_vs  [MROWS * 1024];
__device__ fp16 g_cs  [MROWS * 1024];

// ---------------------------------------------------------------------------
// PTX helpers (base compute_103 features only)
// ---------------------------------------------------------------------------
__device__ __forceinline__ uint32_t smem_u32(const void* p) {
    uint32_t a;
    asm("{ .reg .u64 t; cvta.to.shared.u64 t, %1; cvt.u32.u64 %0, t; }"
        : "=r"(a) : "l"(p));
    return a;
}
#define CP16(dst, src) \
    asm volatile("cp.async.cg.shared.global [%0], [%1], 16;" \
                 :: "r"(dst), "l"(src))
#define CP_COMMIT() asm volatile("cp.async.commit_group;" ::: "memory")
#define CP_WAIT0()  asm volatile("cp.async.wait_group 0;" ::: "memory")
#define CP_WAIT1()  asm volatile("cp.async.wait_group 1;" ::: "memory")

__device__ __forceinline__ void ldsm4(uint32_t addr, uint32_t& r0, uint32_t& r1,
                                      uint32_t& r2, uint32_t& r3) {
    asm volatile("ldmatrix.sync.aligned.m8n8.x4.shared.b16 {%0,%1,%2,%3}, [%4];"
                 : "=r"(r0), "=r"(r1), "=r"(r2), "=r"(r3) : "r"(addr));
}
__device__ __forceinline__ void ldsm4t(uint32_t addr, uint32_t& r0, uint32_t& r1,
                                       uint32_t& r2, uint32_t& r3) {
    asm volatile("ldmatrix.sync.aligned.m8n8.x4.trans.shared.b16 {%0,%1,%2,%3}, [%4];"
                 : "=r"(r0), "=r"(r1), "=r"(r2), "=r"(r3) : "r"(addr));
}
// D += A*B  (m16n8k16, fp16 in, fp32 accum)
__device__ __forceinline__ void mma16816(float* c, uint32_t a0, uint32_t a1,
                                         uint32_t a2, uint32_t a3,
                                         uint32_t b0, uint32_t b1) {
    asm volatile(
        "mma.sync.aligned.m16n8k16.row.col.f32.f16.f16.f32 "
        "{%0,%1,%2,%3}, {%4,%5,%6,%7}, {%8,%9}, {%0,%1,%2,%3};"
        : "+f"(c[0]), "+f"(c[1]), "+f"(c[2]), "+f"(c[3])
        : "r"(a0), "r"(a1), "r"(a2), "r"(a3), "r"(b0), "r"(b1));
}
__device__ __forceinline__ uint32_t packh(float a, float b) {
    __half2 t = __floats2half2_rn(a, b);
    return *(uint32_t*)&t;
}
__device__ __forceinline__ float ex2(float x) {
    float y;
    asm("ex2.approx.f32 %0, %1;" : "=f"(y) : "f"(x));
    return y;
}

// ---------------------------------------------------------------------------
// fp32 [R][1024] -> rounded fp16 [R][1024]
// ---------------------------------------------------------------------------
__global__ __launch_bounds__(256)
void round_kernel(const float* __restrict__ in, fp16* __restrict__ out, int n4) {
    int i = blockIdx.x * blockDim.x + threadIdx.x;
    if (i >= n4) return;
    float4 v = ((const float4*)in)[i];
    uint32_t* o = (uint32_t*)(out + (size_t)i * 4);
    o[0] = packh(v.x, v.y);
    o[1] = packh(v.z, v.w);
}

// Round the 4 weight matrices to fp16 [N][1024] (blockIdx.y selects).
// W_Q (y==0) pre-scaled by 0.125*log2(e): scores come out in log2 units.
__global__ __launch_bounds__(256)
void round_w4(const float* __restrict__ w0, const float* __restrict__ w1,
              const float* __restrict__ w2, const float* __restrict__ w3,
              fp16* __restrict__ wqkv, fp16* __restrict__ wos, int n4) {
    int i = blockIdx.x * blockDim.x + threadIdx.x;
    if (i >= n4) return;
    int y = blockIdx.y;
    const float* src = (y == 0) ? w0 : (y == 1) ? w1 : (y == 2) ? w2 : w3;
    fp16* dst = (y < 3) ? wqkv + (size_t)y * DMODEL * DMODEL : wos;
    float s = (y == 0) ? 0.18033688f : 1.0f;   // 0.125 * log2(e)
    float4 v = ((const float4*)src)[i];
    uint32_t* o = (uint32_t*)(dst + (size_t)i * 4);
    o[0] = packh(v.x * s, v.y * s);
    o[1] = packh(v.z * s, v.w * s);
}

// ---------------------------------------------------------------------------
// Tensor-core GEMM: C[m][n] = A . B, both fp16 single-term, K = 1024.
// A [rows][1024], B [NB][1024]. CTA tile 128x256, 512 thr, warp tile 64x32.
// 3-stage cp.async ring, one __syncthreads per chunk (16 chunks of K=64).
// EPI 0: rounded fp16 to q/k/v (selected by n; layout = natural).
// EPI 1: fp32 + bias.
// ---------------------------------------------------------------------------
#define G_STRIDE 144                    // bytes per smem row (128B data + pad)
#define G_ASTG   (128 * G_STRIDE)       // 18432
#define G_BSTG   (256 * G_STRIDE)       // 36864
#define G_STAGE  (G_ASTG + G_BSTG)      // 55296
#define G_SMEM   (3 * G_STAGE)          // 165888
#define NCHUNK 16

__device__ __forceinline__ void gemm_prefetch(const fp16* A, const fp16* B,
                                              int m0, int n0, int c,
                                              uint32_t stg, int tid) {
    int ac = c * 64;
    int bc = c * 64;
    const uint32_t sa = stg;
    const uint32_t sb = stg + G_ASTG;
#pragma unroll
    for (int it = 0; it < 2; it++) {
        int idx = tid + it * 512;          // 0..1023
        int row = idx >> 3, seg = idx & 7;
        CP16(sa + row * G_STRIDE + seg * 16,
             A + (size_t)(m0 + row) * 1024 + ac + seg * 8);
    }
#pragma unroll
    for (int it = 0; it < 4; it++) {
        int idx = tid + it * 512;          // 0..2047
        int row = idx >> 3, seg = idx & 7;
        CP16(sb + row * G_STRIDE + seg * 16,
             B + (size_t)(n0 + row) * 1024 + bc + seg * 8);
    }
}

template <int EPI>
__global__ __launch_bounds__(512, 1)
void mma_gemm(const fp16* __restrict__ A, const fp16* __restrict__ B,
              float* __restrict__ Cf,
              fp16* __restrict__ Cq, fp16* __restrict__ Ck, fp16* __restrict__ Cv,
              const float* __restrict__ bias) {
    extern __shared__ char smem[];
    const uint32_t sbase = smem_u32(smem);
    const int tid = threadIdx.x;
    const int w = tid >> 5, L = tid & 31;
    const int g = L >> 2, cq = L & 3;
    const int wm = w >> 3, wn = w & 7;       // 2 x 8 warp grid
    const int m0 = blockIdx.y * 128, n0 = blockIdx.x * 256;
    const int quad = L >> 3, l8 = L & 7;

    float acc[4][4][4];                       // 64 fp32 per thread
#pragma unroll
    for (int i = 0; i < 4; i++)
#pragma unroll
        for (int j = 0; j < 4; j++)
#pragma unroll
            for (int k = 0; k < 4; k++) acc[i][j][k] = 0.0f;

    gemm_prefetch(A, B, m0, n0, 0, sbase, tid);
    CP_COMMIT();
    gemm_prefetch(A, B, m0, n0, 1, sbase + G_STAGE, tid);
    CP_COMMIT();

    int stage = 0;
    for (int c = 0; c < NCHUNK; c++) {
        if (c == NCHUNK - 1) { CP_WAIT0(); } else { CP_WAIT1(); }
        __syncthreads();
        if (c + 2 < NCHUNK) {
            int s2 = stage + 2; if (s2 >= 3) s2 -= 3;
            gemm_prefetch(A, B, m0, n0, c + 2, sbase + s2 * G_STAGE, tid);
            CP_COMMIT();
        }
        const uint32_t sa = sbase + stage * G_STAGE;
        const uint32_t sb = sa + G_ASTG;

#pragma unroll
        for (int ks = 0; ks < 4; ks++) {
            uint32_t af[4][4];
#pragma unroll
            for (int i = 0; i < 4; i++) {
                int r = wm * 64 + i * 16 + (quad & 1) * 8 + l8;
                int kof = ks * 16 + (quad >> 1) * 8;
                ldsm4(sa + r * G_STRIDE + kof * 2,
                      af[i][0], af[i][1], af[i][2], af[i][3]);
            }
            uint32_t bfr[2][4];
#pragma unroll
            for (int p = 0; p < 2; p++) {
                int nr = wn * 32 + p * 16 + (quad >> 1) * 8 + l8;
                int kof = ks * 16 + (quad & 1) * 8;
                ldsm4(sb + nr * G_STRIDE + kof * 2,
                      bfr[p][0], bfr[p][1], bfr[p][2], bfr[p][3]);
            }
#pragma unroll
            for (int i = 0; i < 4; i++)
#pragma unroll
                for (int p = 0; p < 2; p++) {
                    mma16816(acc[i][2 * p], af[i][0], af[i][1], af[i][2], af[i][3],
                             bfr[p][0], bfr[p][1]);
                    mma16816(acc[i][2 * p + 1], af[i][0], af[i][1], af[i][2], af[i][3],
                             bfr[p][2], bfr[p][3]);
                }
        }
        stage++; if (stage == 3) stage = 0;
    }

    // Epilogue
#pragma unroll
    for (int i = 0; i < 4; i++) {
        int r0 = m0 + wm * 64 + i * 16 + g;
        int r1 = r0 + 8;
#pragma unroll
        for (int j = 0; j < 4; j++) {
            int col = n0 + wn * 32 + j * 8 + 2 * cq;
            float v0 = acc[i][j][0], v1 = acc[i][j][1];
            float v2 = acc[i][j][2], v3 = acc[i][j][3];
            if (EPI == 1) {
                float b0 = bias[col], b1 = bias[col + 1];
                *(float2*)(Cf + (size_t)r0 * 1024 + col) = make_float2(v0 + b0, v1 + b1);
                *(float2*)(Cf + (size_t)r1 * 1024 + col) = make_float2(v2 + b0, v3 + b1);
            } else {
                int mat = col >> 10, cc = col & 1023;
                fp16* Cb = (mat == 0) ? Cq : (mat == 1) ? Ck : Cv;
                *(uint32_t*)(Cb + (size_t)r0 * 1024 + cc) = packh(v0, v1);
                *(uint32_t*)(Cb + (size_t)r1 * 1024 + cc) = packh(v2, v3);
            }
        }
    }
}

// ---------------------------------------------------------------------------
// Tensor-core flash attention, fp16 single-term, log2-domain softmax.
// Load-balanced: CTA p handles q-blocks (31-p) then (p): 33 tiles each,
// grid (16, 32) = 512 CTAs -> one balanced wave at 4 CTA/SM.
// l via ones-MMA. Fully-padded KV tiles skipped (mask monotone).
// ---------------------------------------------------------------------------
#define K_STRIDE 144                  // 64 fp16 per key row + pad
#define V_STRIDE 144
#define K_TILE   (64 * K_STRIDE)      // 9216
#define V_TILE   (64 * V_STRIDE)      // 9216
#define A_STAGE  (K_TILE + V_TILE)    // 18432
#define A_PAD_OFF (2 * A_STAGE)       // 36864
#define A_SMEM   (A_PAD_OFF + 512)    // 37376
#define HONES 0x3C003C00u             // (1.0h, 1.0h)

__device__ __forceinline__ void attn_prefetch(const fp16* KS, const fp16* VS,
                                              const int* amask, char* smem,
                                              uint32_t sbase, int b, int h,
                                              int kt, int st, int tid) {
    const uint32_t kb = sbase + st * A_STAGE;
    const uint32_t vb = kb + K_TILE;
    const fp16* ksrc = KS + ((size_t)(b * NSEQ + kt)) * 1024 + h * 64;
    const fp16* vsrc = VS + ((size_t)(b * NSEQ + kt)) * 1024 + h * 64;
#pragma unroll
    for (int it = 0; it < 4; it++) {
        int idx = tid + it * 128;
        int row = idx >> 3, seg = idx & 7;
        CP16(kb + row * K_STRIDE + seg * 16, ksrc + (size_t)row * 1024 + seg * 8);
    }
#pragma unroll
    for (int it = 0; it < 4; it++) {
        int idx = tid + it * 128;
        int row = idx >> 3, seg = idx & 7;
        CP16(vb + row * V_STRIDE + seg * 16, vsrc + (size_t)row * 1024 + seg * 8);
    }
    if (tid < 64) {
        float pv = amask[b * NSEQ + kt + tid] ? 0.0f : -1e30f;
        *(float*)(smem + A_PAD_OFF + st * 256 + tid * 4) = pv;
    }
}

__global__ __launch_bounds__(128, 4)
void attn_mma(const fp16* __restrict__ QS, const fp16* __restrict__ KS,
              const fp16* __restrict__ VS, const int* __restrict__ amask,
              fp16* __restrict__ CS) {
    extern __shared__ char smem[];
    const uint32_t sbase = smem_u32(smem);
    const int tid = threadIdx.x;
    const int w = tid >> 5, L = tid & 31;
    const int g = L >> 2, cq = L & 3;
    const int quad = L >> 3, l8 = L & 7;
    const int pr = blockIdx.x;               // 0..15
    const int bh = blockIdx.y;
    const int b = bh >> 4, h = bh & 15;

    for (int seg = 0; seg < 2; seg++) {
        const int qb = (seg == 0) ? (31 - pr) : pr;
        const int m0 = qb * 64;
        const int rowA = m0 + w * 16 + g;
        const int rowB = rowA + 8;

        // Q fragments: 4 k-steps (single fp16 term)
        uint32_t qa[4][4];
        {
            const fp16* qA = QS + (size_t)(b * NSEQ + rowA) * 1024 + h * 64;
            const fp16* qB = QS + (size_t)(b * NSEQ + rowB) * 1024 + h * 64;
#pragma unroll
            for (int s = 0; s < 4; s++) {
                qa[s][0] = *(const uint32_t*)(qA + s * 16 + 2 * cq);
                qa[s][1] = *(const uint32_t*)(qB + s * 16 + 2 * cq);
                qa[s][2] = *(const uint32_t*)(qA + s * 16 + 2 * cq + 8);
                qa[s][3] = *(const uint32_t*)(qB + s * 16 + 2 * cq + 8);
            }
        }

        float co[8][4];
#pragma unroll
        for (int d = 0; d < 8; d++)
#pragma unroll
            for (int k = 0; k < 4; k++) co[d][k] = 0.0f;
        float lacc[4] = {0.0f, 0.0f, 0.0f, 0.0f};
        float mx0 = -1e30f, mx1 = -1e30f;

        const int nt = qb + 1;
        __syncthreads();   // smem stage reuse across segments
        attn_prefetch(KS, VS, amask, smem, sbase, b, h, 0, 0, tid);
        CP_COMMIT();

        for (int t = 0; t < nt; t++) {
            const int kt = t * 64;
            const int st = t & 1;
            CP_WAIT0();
            __syncthreads();
            if (t + 1 < nt) {
                attn_prefetch(KS, VS, amask, smem, sbase, b, h, (t + 1) * 64,
                              (t + 1) & 1, tid);
                CP_COMMIT();
            }

            const uint32_t kb = sbase + st * A_STAGE;
            const uint32_t vb = kb + K_TILE;
            const float* padf = (const float*)(smem + A_PAD_OFF + st * 256);

            // Fully-padded tile (mask monotone): nothing to do.
            if (padf[0] < -1e29f) continue;

            // ---- scores: q x Kh ----
            float sc[8][4];
#pragma unroll
            for (int f = 0; f < 8; f++)
#pragma unroll
                for (int k = 0; k < 4; k++) sc[f][k] = 0.0f;

#pragma unroll
            for (int ks = 0; ks < 4; ks++) {
                const int kof = ks * 16 + (quad & 1) * 8;
#pragma unroll
                for (int p = 0; p < 4; p++) {
                    uint32_t b0, b1, b2, b3;
                    int krow = p * 16 + (quad >> 1) * 8 + l8;
                    ldsm4(kb + krow * K_STRIDE + kof * 2, b0, b1, b2, b3);
                    mma16816(sc[2 * p], qa[ks][0], qa[ks][1], qa[ks][2], qa[ks][3],
                             b0, b1);
                    mma16816(sc[2 * p + 1], qa[ks][0], qa[ks][1], qa[ks][2], qa[ks][3],
                             b2, b3);
                }
            }

            // ---- mask + row max (log2 domain) ----
            const bool diag = (kt == m0);
            float mn0 = mx0, mn1 = mx1;
#pragma unroll
            for (int f = 0; f < 8; f++) {
                float2 pd = *(const float2*)(padf + f * 8 + 2 * cq);
                int k0 = kt + f * 8 + 2 * cq;
                float s0 = sc[f][0] + pd.x;
                float s1 = sc[f][1] + pd.y;
                float s2 = sc[f][2] + pd.x;
                float s3 = sc[f][3] + pd.y;
                if (diag) {
                    if (k0 > rowA) s0 = -1e30f;
                    if (k0 + 1 > rowA) s1 = -1e30f;
                    if (k0 > rowB) s2 = -1e30f;
                    if (k0 + 1 > rowB) s3 = -1e30f;
                }
                sc[f][0] = s0; sc[f][1] = s1; sc[f][2] = s2; sc[f][3] = s3;
                mn0 = fmaxf(mn0, fmaxf(s0, s1));
                mn1 = fmaxf(mn1, fmaxf(s2, s3));
            }
            mn0 = fmaxf(mn0, __shfl_xor_sync(0xffffffffu, mn0, 1));
            mn0 = fmaxf(mn0, __shfl_xor_sync(0xffffffffu, mn0, 2));
            mn1 = fmaxf(mn1, __shfl_xor_sync(0xffffffffu, mn1, 1));
            mn1 = fmaxf(mn1, __shfl_xor_sync(0xffffffffu, mn1, 2));

            const float corr0 = ex2(mx0 - mn0);
            const float corr1 = ex2(mx1 - mn1);
            mx0 = mn0; mx1 = mn1;
#pragma unroll
            for (int d = 0; d < 8; d++) {
                co[d][0] *= corr0; co[d][1] *= corr0;
                co[d][2] *= corr1; co[d][3] *= corr1;
            }
            lacc[0] *= corr0; lacc[1] *= corr0;
            lacc[2] *= corr1; lacc[3] *= corr1;

            // ---- P = ex2(s - max), fp16 fragments ----
            uint32_t phA[8], phB[8];
#pragma unroll
            for (int f = 0; f < 8; f++) {
                float p0 = ex2(sc[f][0] - mn0), p1 = ex2(sc[f][1] - mn0);
                float p2 = ex2(sc[f][2] - mn1), p3 = ex2(sc[f][3] - mn1);
                phA[f] = packh(p0, p1);
                phB[f] = packh(p2, p3);
            }

            // ---- l += P @ ones ----
#pragma unroll
            for (int kk = 0; kk < 4; kk++)
                mma16816(lacc, phA[2 * kk], phB[2 * kk],
                         phA[2 * kk + 1], phB[2 * kk + 1], HONES, HONES);

            // ---- O += P @ V ----
#pragma unroll
            for (int kk = 0; kk < 4; kk++) {
                uint32_t a0 = phA[2 * kk], a1 = phB[2 * kk];
                uint32_t a2 = phA[2 * kk + 1], a3 = phB[2 * kk + 1];
#pragma unroll
                for (int dp = 0; dp < 4; dp++) {
                    int key = kk * 16 + (quad & 1) * 8 + l8;
                    int dkc = (2 * dp + (quad >> 1)) * 8;
                    uint32_t vh0, vh1, vh2, vh3;
                    ldsm4t(vb + key * V_STRIDE + dkc * 2, vh0, vh1, vh2, vh3);
                    mma16816(co[2 * dp],     a0, a1, a2, a3, vh0, vh1);
                    mma16816(co[2 * dp + 1], a0, a1, a2, a3, vh2, vh3);
                }
            }
        }

        // ---- finalize: l in lacc[0] (rowA) / lacc[2] (rowB) ----
        const float inv0 = 1.0f / lacc[0], inv1 = 1.0f / lacc[2];
#pragma unroll
        for (int d = 0; d < 8; d++) {
            int dk = d * 8 + 2 * cq;
            size_t bA = (size_t)(b * NSEQ + rowA) * 1024 + h * 64 + dk;
            size_t bB = (size_t)(b * NSEQ + rowB) * 1024 + h * 64 + dk;
            *(uint32_t*)(CS + bA) = packh(co[d][0] * inv0, co[d][1] * inv0);
            *(uint32_t*)(CS + bB) = packh(co[d][2] * inv1, co[d][3] * inv1);
        }
    }
}

// ---------------------------------------------------------------------------
// Launch
// ---------------------------------------------------------------------------
extern "C" void kernel_launch(void* const* d_in, const int* in_sizes, int n_in,
                              void* d_out, int out_size) {
    const float* x     = (const float*)d_in[0];
    const int*   amask = (const int*)d_in[1];
    const float* W_Q   = (const float*)d_in[2];
    const float* W_K   = (const float*)d_in[3];
    const float* W_V   = (const float*)d_in[4];
    const float* W_out = (const float*)d_in[5];
    const float* b_out = (const float*)d_in[6];
    float* out = (float*)d_out;

    fp16 *xs, *wqkv, *wos, *qs, *ks, *vs, *cs;
    cudaGetSymbolAddress((void**)&xs, g_xs);
    cudaGetSymbolAddress((void**)&wqkv, g_wqkv);
    cudaGetSymbolAddress((void**)&wos, g_wos);
    cudaGetSymbolAddress((void**)&qs, g_qs);
    cudaGetSymbolAddress((void**)&ks, g_ks);
    cudaGetSymbolAddress((void**)&vs, g_vs);
    cudaGetSymbolAddress((void**)&cs, g_cs);

    cudaFuncSetAttribute(mma_gemm<0>, cudaFuncAttributeMaxDynamicSharedMemorySize, G_SMEM);
    cudaFuncSetAttribute(mma_gemm<1>, cudaFuncAttributeMaxDynamicSharedMemorySize, G_SMEM);
    cudaFuncSetAttribute(attn_mma, cudaFuncAttributeMaxDynamicSharedMemorySize, A_SMEM);

    const int nx4 = MROWS * DMODEL / 4;
    const int nw4 = DMODEL * DMODEL / 4;
    round_kernel<<<(nx4 + 255) / 256, 256>>>(x, xs, nx4);
    dim3 wgrid((nw4 + 255) / 256, 4);
    round_w4<<<wgrid, 256>>>(W_Q, W_K, W_V, W_out, wqkv, wos, nw4);

    dim3 qkvgrid(3 * DMODEL / 256, MROWS / 128);   // (12, 32)
    mma_gemm<0><<<qkvgrid, 512, G_SMEM>>>(xs, wqkv, nullptr, qs, ks, vs, nullptr);

    dim3 agrid(16, BATCH * NHEAD);                 // (16, 32) balanced pairs
    attn_mma<<<agrid, 128, A_SMEM>>>(qs, ks, vs, amask, cs);

    dim3 ogrid(DMODEL / 256, MROWS / 128);         // (4, 32)
    mma_gemm<1><<<ogrid, 512, G_SMEM>>>(cs, wos, out, nullptr, nullptr, nullptr, b_out);
}

// round 17
// speedup vs baseline: 1.9131x; 1.0272x over previous
#include <cuda_runtime.h>
#include <cuda_fp16.h>
#include <cstdint>

// Problem constants
#define BATCH 2
#define NSEQ  2048
#define DMODEL 1024
#define NHEAD 16
#define DK    64
#define MROWS (BATCH * NSEQ)   // 4096

typedef __half fp16;

// ---------------------------------------------------------------------------
// Scratch (allocation-free rule: __device__ globals)
// All activations single rounded fp16 [rows][1024].
// q/k/v: per-head layout == natural GEMM output layout (head h at h*64).
// Weights rounded fp16: wqkv [3072][1024] (W_Q pre-scaled by 0.125*log2e),
// wos [1024][1024].  K/V rows past the sequence length are never written
// (skip predicate is replay-invariant) and stay zero-initialized.
// ---------------------------------------------------------------------------
__device__ fp16 g_xs  [MROWS * 1024];
__device__ fp16 g_wqkv[3 * DMODEL * DMODEL];
__device__ fp16 g_wos [DMODEL * DMODEL];
__device__ fp16 g_qs  [MROWS * 1024];
__device__ fp16 g_ks  [MROWS * 1024];
__device__ fp16 g_vs  [MROWS * 1024];
__device__ fp16 g_cs  [MROWS * 1024];
__device__ int  g_len [BATCH];

// ---------------------------------------------------------------------------
// PTX helpers (base compute_103 features only)
// ---------------------------------------------------------------------------
__device__ __forceinline__ uint32_t smem_u32(const void* p) {
    uint32_t a;
    asm("{ .reg .u64 t; cvta.to.shared.u64 t, %1; cvt.u32.u64 %0, t; }"
        : "=r"(a) : "l"(p));
    return a;
}
#define CP16(dst, src) \
    asm volatile("cp.async.cg.shared.global [%0], [%1], 16;" \
                 :: "r"(dst), "l"(src))
#define CP_COMMIT() asm volatile("cp.async.commit_group;" ::: "memory")
#define CP_WAIT0()  asm volatile("cp.async.wait_group 0;" ::: "memory")
#define CP_WAIT1()  asm volatile("cp.async.wait_group 1;" ::: "memory")

__device__ __forceinline__ void ldsm4(uint32_t addr, uint32_t& r0, uint32_t& r1,
                                      uint32_t& r2, uint32_t& r3) {
    asm volatile("ldmatrix.sync.aligned.m8n8.x4.shared.b16 {%0,%1,%2,%3}, [%4];"
                 : "=r"(r0), "=r"(r1), "=r"(r2), "=r"(r3) : "r"(addr));
}
__device__ __forceinline__ void ldsm4t(uint32_t addr, uint32_t& r0, uint32_t& r1,
                                       uint32_t& r2, uint32_t& r3) {
    asm volatile("ldmatrix.sync.aligned.m8n8.x4.trans.shared.b16 {%0,%1,%2,%3}, [%4];"
                 : "=r"(r0), "=r"(r1), "=r"(r2), "=r"(r3) : "r"(addr));
}
// D += A*B  (m16n8k16, fp16 in, fp32 accum)
__device__ __forceinline__ void mma16816(float* c, uint32_t a0, uint32_t a1,
                                         uint32_t a2, uint32_t a3,
                                         uint32_t b0, uint32_t b1) {
    asm volatile(
        "mma.sync.aligned.m16n8k16.row.col.f32.f16.f16.f32 "
        "{%0,%1,%2,%3}, {%4,%5,%6,%7}, {%8,%9}, {%0,%1,%2,%3};"
        : "+f"(c[0]), "+f"(c[1]), "+f"(c[2]), "+f"(c[3])
        : "r"(a0), "r"(a1), "r"(a2), "r"(a3), "r"(b0), "r"(b1));
}
__device__ __forceinline__ uint32_t packh(float a, float b) {
    __half2 t = __floats2half2_rn(a, b);
    return *(uint32_t*)&t;
}
__device__ __forceinline__ float ex2(float x) {
    float y;
    asm("ex2.approx.f32 %0, %1;" : "=f"(y) : "f"(x));
    return y;
}
__device__ __forceinline__ uint32_t ex2h2(uint32_t x) {
    uint32_t y;
    asm("ex2.approx.f16x2 %0, %1;" : "=r"(y) : "r"(x));
    return y;
}

// ---------------------------------------------------------------------------
// Sequence lengths from the (monotone) attention mask.
// ---------------------------------------------------------------------------
__global__ __launch_bounds__(256)
void len_kernel(const int* __restrict__ amask) {
    int b = blockIdx.x;
    int s = 0;
    for (int i = threadIdx.x; i < NSEQ; i += 256) s += amask[b * NSEQ + i];
#pragma unroll
    for (int o = 16; o > 0; o >>= 1) s += __shfl_xor_sync(0xffffffffu, s, o);
    __shared__ int ws[8];
    if ((threadIdx.x & 31) == 0) ws[threadIdx.x >> 5] = s;
    __syncthreads();
    if (threadIdx.x == 0) {
        int v = 0;
#pragma unroll
        for (int i = 0; i < 8; i++) v += ws[i];
        g_len[b] = v;
    }
}

// ---------------------------------------------------------------------------
// fp32 [R][1024] -> rounded fp16 [R][1024]
// ---------------------------------------------------------------------------
__global__ __launch_bounds__(256)
void round_kernel(const float* __restrict__ in, fp16* __restrict__ out, int n4) {
    int i = blockIdx.x * blockDim.x + threadIdx.x;
    if (i >= n4) return;
    float4 v = ((const float4*)in)[i];
    uint32_t* o = (uint32_t*)(out + (size_t)i * 4);
    o[0] = packh(v.x, v.y);
    o[1] = packh(v.z, v.w);
}

// Round the 4 weight matrices to fp16 [N][1024] (blockIdx.y selects).
// W_Q (y==0) pre-scaled by 0.125*log2(e): scores come out in log2 units.
__global__ __launch_bounds__(256)
void round_w4(const float* __restrict__ w0, const float* __restrict__ w1,
              const float* __restrict__ w2, const float* __restrict__ w3,
              fp16* __restrict__ wqkv, fp16* __restrict__ wos, int n4) {
    int i = blockIdx.x * blockDim.x + threadIdx.x;
    if (i >= n4) return;
    int y = blockIdx.y;
    const float* src = (y == 0) ? w0 : (y == 1) ? w1 : (y == 2) ? w2 : w3;
    fp16* dst = (y < 3) ? wqkv + (size_t)y * DMODEL * DMODEL : wos;
    float s = (y == 0) ? 0.18033688f : 1.0f;   // 0.125 * log2(e)
    float4 v = ((const float4*)src)[i];
    uint32_t* o = (uint32_t*)(dst + (size_t)i * 4);
    o[0] = packh(v.x * s, v.y * s);
    o[1] = packh(v.z * s, v.w * s);
}

// ---------------------------------------------------------------------------
// Tensor-core GEMM: C[m][n] = A . B, both fp16 single-term, K = 1024.
// A [rows][1024], B [NB][1024]. CTA tile 128x256, 512 thr, warp tile 64x32.
// 3-stage cp.async ring, one __syncthreads per chunk (16 chunks of K=64).
// EPI 0: rounded fp16 to q/k/v; K/V tiles fully past the sequence length
//        are skipped (dead work — consumers never read those rows).
// EPI 1: fp32 + bias.
// ---------------------------------------------------------------------------
#define G_STRIDE 144                    // bytes per smem row (128B data + pad)
#define G_ASTG   (128 * G_STRIDE)       // 18432
#define G_BSTG   (256 * G_STRIDE)       // 36864
#define G_STAGE  (G_ASTG + G_BSTG)      // 55296
#define G_SMEM   (3 * G_STAGE)          // 165888
#define NCHUNK 16

__device__ __forceinline__ void gemm_prefetch(const fp16* A, const fp16* B,
                                              int m0, int n0, int c,
                                              uint32_t stg, int tid) {
    int ac = c * 64;
    int bc = c * 64;
    const uint32_t sa = stg;
    const uint32_t sb = stg + G_ASTG;
#pragma unroll
    for (int it = 0; it < 2; it++) {
        int idx = tid + it * 512;          // 0..1023
        int row = idx >> 3, seg = idx & 7;
        CP16(sa + row * G_STRIDE + seg * 16,
             A + (size_t)(m0 + row) * 1024 + ac + seg * 8);
    }
#pragma unroll
    for (int it = 0; it < 4; it++) {
        int idx = tid + it * 512;          // 0..2047
        int row = idx >> 3, seg = idx & 7;
        CP16(sb + row * G_STRIDE + seg * 16,
             B + (size_t)(n0 + row) * 1024 + bc + seg * 8);
    }
}

template <int EPI>
__global__ __launch_bounds__(512, 1)
void mma_gemm(const fp16* __restrict__ A, const fp16* __restrict__ B,
              float* __restrict__ Cf,
              fp16* __restrict__ Cq, fp16* __restrict__ Ck, fp16* __restrict__ Cv,
              const float* __restrict__ bias) {
    const int m0 = blockIdx.y * 128, n0 = blockIdx.x * 256;
    if (EPI == 0 && n0 >= DMODEL) {
        // K/V output tile: skip if this 128-row block is fully padding.
        int b = m0 >> 11;
        if ((m0 & (NSEQ - 1)) >= g_len[b]) return;
    }

    extern __shared__ char smem[];
    const uint32_t sbase = smem_u32(smem);
    const int tid = threadIdx.x;
    const int w = tid >> 5, L = tid & 31;
    const int g = L >> 2, cq = L & 3;
    const int wm = w >> 3, wn = w & 7;       // 2 x 8 warp grid
    const int quad = L >> 3, l8 = L & 7;

    float acc[4][4][4];                       // 64 fp32 per thread
#pragma unroll
    for (int i = 0; i < 4; i++)
#pragma unroll
        for (int j = 0; j < 4; j++)
#pragma unroll
            for (int k = 0; k < 4; k++) acc[i][j][k] = 0.0f;

    gemm_prefetch(A, B, m0, n0, 0, sbase, tid);
    CP_COMMIT();
    gemm_prefetch(A, B, m0, n0, 1, sbase + G_STAGE, tid);
    CP_COMMIT();

    int stage = 0;
    for (int c = 0; c < NCHUNK; c++) {
        if (c == NCHUNK - 1) { CP_WAIT0(); } else { CP_WAIT1(); }
        __syncthreads();
        if (c + 2 < NCHUNK) {
            int s2 = stage + 2; if (s2 >= 3) s2 -= 3;
            gemm_prefetch(A, B, m0, n0, c + 2, sbase + s2 * G_STAGE, tid);
            CP_COMMIT();
        }
        const uint32_t sa = sbase + stage * G_STAGE;
        const uint32_t sb = sa + G_ASTG;

#pragma unroll
        for (int ks = 0; ks < 4; ks++) {
            uint32_t af[4][4];
#pragma unroll
            for (int i = 0; i < 4; i++) {
                int r = wm * 64 + i * 16 + (quad & 1) * 8 + l8;
                int kof = ks * 16 + (quad >> 1) * 8;
                ldsm4(sa + r * G_STRIDE + kof * 2,
                      af[i][0], af[i][1], af[i][2], af[i][3]);
            }
            uint32_t bfr[2][4];
#pragma unroll
            for (int p = 0; p < 2; p++) {
                int nr = wn * 32 + p * 16 + (quad >> 1) * 8 + l8;
                int kof = ks * 16 + (quad & 1) * 8;
                ldsm4(sb + nr * G_STRIDE + kof * 2,
                      bfr[p][0], bfr[p][1], bfr[p][2], bfr[p][3]);
            }
#pragma unroll
            for (int i = 0; i < 4; i++)
#pragma unroll
                for (int p = 0; p < 2; p++) {
                    mma16816(acc[i][2 * p], af[i][0], af[i][1], af[i][2], af[i][3],
                             bfr[p][0], bfr[p][1]);
                    mma16816(acc[i][2 * p + 1], af[i][0], af[i][1], af[i][2], af[i][3],
                             bfr[p][2], bfr[p][3]);
                }
        }
        stage++; if (stage == 3) stage = 0;
    }

    // Epilogue
#pragma unroll
    for (int i = 0; i < 4; i++) {
        int r0 = m0 + wm * 64 + i * 16 + g;
        int r1 = r0 + 8;
#pragma unroll
        for (int j = 0; j < 4; j++) {
            int col = n0 + wn * 32 + j * 8 + 2 * cq;
            float v0 = acc[i][j][0], v1 = acc[i][j][1];
            float v2 = acc[i][j][2], v3 = acc[i][j][3];
            if (EPI == 1) {
                float b0 = bias[col], b1 = bias[col + 1];
                *(float2*)(Cf + (size_t)r0 * 1024 + col) = make_float2(v0 + b0, v1 + b1);
                *(float2*)(Cf + (size_t)r1 * 1024 + col) = make_float2(v2 + b0, v3 + b1);
            } else {
                int mat = col >> 10, cc = col & 1023;
                fp16* Cb = (mat == 0) ? Cq : (mat == 1) ? Ck : Cv;
                *(uint32_t*)(Cb + (size_t)r0 * 1024 + cc) = packh(v0, v1);
                *(uint32_t*)(Cb + (size_t)r1 * 1024 + cc) = packh(v2, v3);
            }
        }
    }
}

// ---------------------------------------------------------------------------
// Tensor-core flash attention, fp16 single-term, log2-domain softmax.
// Load-balanced: CTA p handles q-blocks (31-p) then (p): 33 tiles each,
// grid (16, 32) = 512 CTAs -> one balanced wave at 4 CTA/SM.
// P via ex2.approx.f16x2 (packed). l via ones-MMA.
// Fully-padded KV tiles skipped; pad-adds skipped on fully-valid tiles;
// rescale vote-skipped when no lane saw a new row max.
// ---------------------------------------------------------------------------
#define K_STRIDE 144                  // 64 fp16 per key row + pad
#define V_STRIDE 144
#define K_TILE   (64 * K_STRIDE)      // 9216
#define V_TILE   (64 * V_STRIDE)      // 9216
#define A_STAGE  (K_TILE + V_TILE)    // 18432
#define A_PAD_OFF (2 * A_STAGE)       // 36864
#define A_SMEM   (A_PAD_OFF + 512)    // 37376
#define HONES 0x3C003C00u             // (1.0h, 1.0h)

__device__ __forceinline__ void attn_prefetch(const fp16* KS, const fp16* VS,
                                              const int* amask, char* smem,
                                              uint32_t sbase, int b, int h,
                                              int kt, int st, int tid) {
    const uint32_t kb = sbase + st * A_STAGE;
    const uint32_t vb = kb + K_TILE;
    const fp16* ksrc = KS + ((size_t)(b * NSEQ + kt)) * 1024 + h * 64;
    const fp16* vsrc = VS + ((size_t)(b * NSEQ + kt)) * 1024 + h * 64;
#pragma unroll
    for (int it = 0; it < 4; it++) {
        int idx = tid + it * 128;
        int row = idx >> 3, seg = idx & 7;
        CP16(kb + row * K_STRIDE + seg * 16, ksrc + (size_t)row * 1024 + seg * 8);
    }
#pragma unroll
    for (int it = 0; it < 4; it++) {
        int idx = tid + it * 128;
        int row = idx >> 3, seg = idx & 7;
        CP16(vb + row * V_STRIDE + seg * 16, vsrc + (size_t)row * 1024 + seg * 8);
    }
    if (tid < 64) {
        float pv = amask[b * NSEQ + kt + tid] ? 0.0f : -1e30f;
        *(float*)(smem + A_PAD_OFF + st * 256 + tid * 4) = pv;
    }
}

__global__ __launch_bounds__(128, 4)
void attn_mma(const fp16* __restrict__ QS, const fp16* __restrict__ KS,
              const fp16* __restrict__ VS, const int* __restrict__ amask,
              fp16* __restrict__ CS) {
    extern __shared__ char smem[];
    const uint32_t sbase = smem_u32(smem);
    const int tid = threadIdx.x;
    const int w = tid >> 5, L = tid & 31;
    const int g = L >> 2, cq = L & 3;
    const int quad = L >> 3, l8 = L & 7;
    const int pr = blockIdx.x;               // 0..15
    const int bh = blockIdx.y;
    const int b = bh >> 4, h = bh & 15;

    for (int seg = 0; seg < 2; seg++) {
        const int qb = (seg == 0) ? (31 - pr) : pr;
        const int m0 = qb * 64;
        const int rowA = m0 + w * 16 + g;
        const int rowB = rowA + 8;

        // Q fragments: 4 k-steps (single fp16 term)
        uint32_t qa[4][4];
        {
            const fp16* qA = QS + (size_t)(b * NSEQ + rowA) * 1024 + h * 64;
            const fp16* qB = QS + (size_t)(b * NSEQ + rowB) * 1024 + h * 64;
#pragma unroll
            for (int s = 0; s < 4; s++) {
                qa[s][0] = *(const uint32_t*)(qA + s * 16 + 2 * cq);
                qa[s][1] = *(const uint32_t*)(qB + s * 16 + 2 * cq);
                qa[s][2] = *(const uint32_t*)(qA + s * 16 + 2 * cq + 8);
                qa[s][3] = *(const uint32_t*)(qB + s * 16 + 2 * cq + 8);
            }
        }

        float co[8][4];
#pragma unroll
        for (int d = 0; d < 8; d++)
#pragma unroll
            for (int k = 0; k < 4; k++) co[d][k] = 0.0f;
        float lacc[4] = {0.0f, 0.0f, 0.0f, 0.0f};
        float mx0 = -1e30f, mx1 = -1e30f;

        const int nt = qb + 1;
        __syncthreads();   // smem stage reuse across segments
        attn_prefetch(KS, VS, amask, smem, sbase, b, h, 0, 0, tid);
        CP_COMMIT();

        for (int t = 0; t < nt; t++) {
            const int kt = t * 64;
            const int st = t & 1;
            CP_WAIT0();
            __syncthreads();
            if (t + 1 < nt) {
                attn_prefetch(KS, VS, amask, smem, sbase, b, h, (t + 1) * 64,
                              (t + 1) & 1, tid);
                CP_COMMIT();
            }

            const uint32_t kb = sbase + st * A_STAGE;
            const uint32_t vb = kb + K_TILE;
            const float* padf = (const float*)(smem + A_PAD_OFF + st * 256);

            // Fully-padded tile (mask monotone): nothing to do.
            if (padf[0] < -1e29f) continue;
            const bool fullvalid = (padf[63] == 0.0f);

            // ---- scores: q x Kh ----
            float sc[8][4];
#pragma unroll
            for (int f = 0; f < 8; f++)
#pragma unroll
                for (int k = 0; k < 4; k++) sc[f][k] = 0.0f;

#pragma unroll
            for (int ks = 0; ks < 4; ks++) {
                const int kof = ks * 16 + (quad & 1) * 8;
#pragma unroll
                for (int p = 0; p < 4; p++) {
                    uint32_t b0, b1, b2, b3;
                    int krow = p * 16 + (quad >> 1) * 8 + l8;
                    ldsm4(kb + krow * K_STRIDE + kof * 2, b0, b1, b2, b3);
                    mma16816(sc[2 * p], qa[ks][0], qa[ks][1], qa[ks][2], qa[ks][3],
                             b0, b1);
                    mma16816(sc[2 * p + 1], qa[ks][0], qa[ks][1], qa[ks][2], qa[ks][3],
                             b2, b3);
                }
            }

            // ---- mask (only when needed) + row max (log2 domain) ----
            if (!fullvalid) {
#pragma unroll
                for (int f = 0; f < 8; f++) {
                    float2 pd = *(const float2*)(padf + f * 8 + 2 * cq);
                    sc[f][0] += pd.x; sc[f][1] += pd.y;
                    sc[f][2] += pd.x; sc[f][3] += pd.y;
                }
            }
            if (kt == m0) {   // diagonal tile: causal mask
#pragma unroll
                for (int f = 0; f < 8; f++) {
                    int k0 = kt + f * 8 + 2 * cq;
                    if (k0 > rowA) sc[f][0] = -1e30f;
                    if (k0 + 1 > rowA) sc[f][1] = -1e30f;
                    if (k0 > rowB) sc[f][2] = -1e30f;
                    if (k0 + 1 > rowB) sc[f][3] = -1e30f;
                }
            }
            float mn0 = mx0, mn1 = mx1;
#pragma unroll
            for (int f = 0; f < 8; f++) {
                mn0 = fmaxf(mn0, fmaxf(sc[f][0], sc[f][1]));
                mn1 = fmaxf(mn1, fmaxf(sc[f][2], sc[f][3]));
            }
            mn0 = fmaxf(mn0, __shfl_xor_sync(0xffffffffu, mn0, 1));
            mn0 = fmaxf(mn0, __shfl_xor_sync(0xffffffffu, mn0, 2));
            mn1 = fmaxf(mn1, __shfl_xor_sync(0xffffffffu, mn1, 1));
            mn1 = fmaxf(mn1, __shfl_xor_sync(0xffffffffu, mn1, 2));

            // ---- rescale only if some lane saw a new max ----
            bool nochg = (mn0 == mx0) && (mn1 == mx1);
            if (!__all_sync(0xffffffffu, nochg)) {
                const float corr0 = ex2(mx0 - mn0);
                const float corr1 = ex2(mx1 - mn1);
#pragma unroll
                for (int d = 0; d < 8; d++) {
                    co[d][0] *= corr0; co[d][1] *= corr0;
                    co[d][2] *= corr1; co[d][3] *= corr1;
                }
                lacc[0] *= corr0; lacc[1] *= corr0;
                lacc[2] *= corr1; lacc[3] *= corr1;
            }
            mx0 = mn0; mx1 = mn1;

            // ---- P = ex2(s - max) via packed f16x2 MUFU ----
            uint32_t phA[8], phB[8];
#pragma unroll
            for (int f = 0; f < 8; f++) {
                phA[f] = ex2h2(packh(sc[f][0] - mn0, sc[f][1] - mn0));
                phB[f] = ex2h2(packh(sc[f][2] - mn1, sc[f][3] - mn1));
            }

            // ---- l += P @ ones ----
#pragma unroll
            for (int kk = 0; kk < 4; kk++)
                mma16816(lacc, phA[2 * kk], phB[2 * kk],
                         phA[2 * kk + 1], phB[2 * kk + 1], HONES, HONES);

            // ---- O += P @ V ----
#pragma unroll
            for (int kk = 0; kk < 4; kk++) {
                uint32_t a0 = phA[2 * kk], a1 = phB[2 * kk];
                uint32_t a2 = phA[2 * kk + 1], a3 = phB[2 * kk + 1];
#pragma unroll
                for (int dp = 0; dp < 4; dp++) {
                    int key = kk * 16 + (quad & 1) * 8 + l8;
                    int dkc = (2 * dp + (quad >> 1)) * 8;
                    uint32_t vh0, vh1, vh2, vh3;
                    ldsm4t(vb + key * V_STRIDE + dkc * 2, vh0, vh1, vh2, vh3);
                    mma16816(co[2 * dp],     a0, a1, a2, a3, vh0, vh1);
                    mma16816(co[2 * dp + 1], a0, a1, a2, a3, vh2, vh3);
                }
            }
        }

        // ---- finalize: l in lacc[0] (rowA) / lacc[2] (rowB) ----
        const float inv0 = 1.0f / lacc[0], inv1 = 1.0f / lacc[2];
#pragma unroll
        for (int d = 0; d < 8; d++) {
            int dk = d * 8 + 2 * cq;
            size_t bA = (size_t)(b * NSEQ + rowA) * 1024 + h * 64 + dk;
            size_t bB = (size_t)(b * NSEQ + rowB) * 1024 + h * 64 + dk;
            *(uint32_t*)(CS + bA) = packh(co[d][0] * inv0, co[d][1] * inv0);
            *(uint32_t*)(CS + bB) = packh(co[d][2] * inv1, co[d][3] * inv1);
        }
    }
}

// ---------------------------------------------------------------------------
// Launch
// ---------------------------------------------------------------------------
extern "C" void kernel_launch(void* const* d_in, const int* in_sizes, int n_in,
                              void* d_out, int out_size) {
    const float* x     = (const float*)d_in[0];
    const int*   amask = (const int*)d_in[1];
    const float* W_Q   = (const float*)d_in[2];
    const float* W_K   = (const float*)d_in[3];
    const float* W_V   = (const float*)d_in[4];
    const float* W_out = (const float*)d_in[5];
    const float* b_out = (const float*)d_in[6];
    float* out = (float*)d_out;

    fp16 *xs, *wqkv, *wos, *qs, *ks, *vs, *cs;
    cudaGetSymbolAddress((void**)&xs, g_xs);
    cudaGetSymbolAddress((void**)&wqkv, g_wqkv);
    cudaGetSymbolAddress((void**)&wos, g_wos);
    cudaGetSymbolAddress((void**)&qs, g_qs);
    cudaGetSymbolAddress((void**)&ks, g_ks);
    cudaGetSymbolAddress((void**)&vs, g_vs);
    cudaGetSymbolAddress((void**)&cs, g_cs);

    cudaFuncSetAttribute(mma_gemm<0>, cudaFuncAttributeMaxDynamicSharedMemorySize, G_SMEM);
    cudaFuncSetAttribute(mma_gemm<1>, cudaFuncAttributeMaxDynamicSharedMemorySize, G_SMEM);
    cudaFuncSetAttribute(attn_mma, cudaFuncAttributeMaxDynamicSharedMemorySize, A_SMEM);

    const int nx4 = MROWS * DMODEL / 4;
    const int nw4 = DMODEL * DMODEL / 4;
    len_kernel<<<BATCH, 256>>>(amask);
    round_kernel<<<(nx4 + 255) / 256, 256>>>(x, xs, nx4);
    dim3 wgrid((nw4 + 255) / 256, 4);
    round_w4<<<wgrid, 256>>>(W_Q, W_K, W_V, W_out, wqkv, wos, nw4);

    dim3 qkvgrid(3 * DMODEL / 256, MROWS / 128);   // (12, 32)
    mma_gemm<0><<<qkvgrid, 512, G_SMEM>>>(xs, wqkv, nullptr, qs, ks, vs, nullptr);

    dim3 agrid(16, BATCH * NHEAD);                 // (16, 32) balanced pairs
    attn_mma<<<agrid, 128, A_SMEM>>>(qs, ks, vs, amask, cs);

    dim3 ogrid(DMODEL / 256, MROWS / 128);         // (4, 32)
    mma_gemm<1><<<ogrid, 512, G_SMEM>>>(cs, wos, out, nullptr, nullptr, nullptr, b_out);
}